// round 1
// baseline (speedup 1.0000x reference)
#include <cuda_runtime.h>
#include <cuda_bf16.h>
#include <math.h>

// Problem dims
#define BB 32
#define SS 512
#define HH 128
#define NHEADS 4
#define DD 32
#define FFD 512
#define NN 16
#define SNN 64
#define ROWS (BB*SS)          // 16384

// ---------------- static device scratch ----------------
__device__ float g_xn  [ROWS*HH];
__device__ float g_q   [ROWS*HH];
__device__ float g_k   [ROWS*HH];
__device__ float g_v   [ROWS*HH];
__device__ float g_attn[ROWS*HH];
__device__ float g_x1  [ROWS*HH];
__device__ float g_h   [ROWS*HH];
__device__ float g_ffh [ROWS*FFD];
__device__ float g_x2  [ROWS*HH];
__device__ float g_A   [ROWS*HH];
__device__ float g_xnei[BB*NN*HH];
__device__ float g_Bn  [BB*NN*HH];
__device__ float g_Wd  [HH*HH];
__device__ float g_Wnc [HH*HH];

// ---------------- helpers ----------------
__device__ __forceinline__ float gelu_tanh(float x) {
    float t = tanhf(0.7978845608028654f * (x + 0.044715f * x * x * x));
    return 0.5f * x * (1.0f + t);
}

// ---------------- prep au weights: Wd = W1-W3, Wnc = W3+W4 ----------------
__global__ void prep_au_kernel(const float* __restrict__ au_w1,
                               float* __restrict__ Wd, float* __restrict__ Wnc) {
    int idx = blockIdx.x * blockDim.x + threadIdx.x;
    if (idx < HH * HH) {
        int h = idx >> 7, j = idx & 127;
        float w1 = au_w1[h * HH + j];
        float w3 = au_w1[(256 + h) * HH + j];
        float w4 = au_w1[(384 + h) * HH + j];
        Wd[idx]  = w1 - w3;
        Wnc[idx] = w3 + w4;
    }
}

// ---------------- layernorm: one block per row, 128 threads ----------------
__global__ void ln_kernel(const float* __restrict__ x, const float* __restrict__ g,
                          const float* __restrict__ b, float* __restrict__ y) {
    int row = blockIdx.x;
    int t = threadIdx.x;
    float v = x[(size_t)row * HH + t];
    float s = v, s2 = v * v;
    #pragma unroll
    for (int o = 16; o > 0; o >>= 1) {
        s  += __shfl_xor_sync(0xffffffffu, s, o);
        s2 += __shfl_xor_sync(0xffffffffu, s2, o);
    }
    __shared__ float ws[8];
    if ((t & 31) == 0) { ws[t >> 5] = s; ws[4 + (t >> 5)] = s2; }
    __syncthreads();
    s  = ws[0] + ws[1] + ws[2] + ws[3];
    s2 = ws[4] + ws[5] + ws[6] + ws[7];
    float mean = s * (1.0f / HH);
    float var = s2 * (1.0f / HH) - mean * mean;
    float rs = rsqrtf(var + 1e-6f);
    y[(size_t)row * HH + t] = (v - mean) * rs * g[t] + b[t];
}

// ---------------- generic SGEMM: C = act(A@W + bias) + res ----------------
// BM=BN=64, BK=16, 256 threads (16x16), TM=TN=4
#define GBM 64
#define GBN 64
#define GBK 16
__global__ void sgemm_kernel(const float* __restrict__ A, const float* __restrict__ W,
                             const float* __restrict__ bias, const float* __restrict__ res,
                             float* __restrict__ C, int M, int K, int Nc, int act) {
    __shared__ float As[GBK][GBM + 1];
    __shared__ float Ws[GBK][GBN];
    int bm = blockIdx.y * GBM, bn = blockIdx.x * GBN;
    int tid = threadIdx.x;
    int ty = tid >> 4, tx = tid & 15;
    float acc[4][4] = {};
    for (int k0 = 0; k0 < K; k0 += GBK) {
        {
            int r = tid >> 2, c = (tid & 3) * 4;
            float4 a4 = *(const float4*)&A[(size_t)(bm + r) * K + k0 + c];
            As[c + 0][r] = a4.x; As[c + 1][r] = a4.y; As[c + 2][r] = a4.z; As[c + 3][r] = a4.w;
        }
        {
            int r = tid >> 4, c = (tid & 15) * 4;
            float4 w4 = *(const float4*)&W[(size_t)(k0 + r) * Nc + bn + c];
            *(float4*)&Ws[r][c] = w4;
        }
        __syncthreads();
        #pragma unroll
        for (int kk = 0; kk < GBK; kk++) {
            float a0 = As[kk][ty * 4 + 0];
            float a1 = As[kk][ty * 4 + 1];
            float a2 = As[kk][ty * 4 + 2];
            float a3 = As[kk][ty * 4 + 3];
            float4 w = *(float4*)&Ws[kk][tx * 4];
            acc[0][0] += a0 * w.x; acc[0][1] += a0 * w.y; acc[0][2] += a0 * w.z; acc[0][3] += a0 * w.w;
            acc[1][0] += a1 * w.x; acc[1][1] += a1 * w.y; acc[1][2] += a1 * w.z; acc[1][3] += a1 * w.w;
            acc[2][0] += a2 * w.x; acc[2][1] += a2 * w.y; acc[2][2] += a2 * w.z; acc[2][3] += a2 * w.w;
            acc[3][0] += a3 * w.x; acc[3][1] += a3 * w.y; acc[3][2] += a3 * w.z; acc[3][3] += a3 * w.w;
        }
        __syncthreads();
    }
    #pragma unroll
    for (int i = 0; i < 4; i++) {
        int row = bm + ty * 4 + i;
        #pragma unroll
        for (int j = 0; j < 4; j++) {
            int col = bn + tx * 4 + j;
            float v = acc[i][j];
            if (bias) v += bias[col];
            if (act == 1) v = gelu_tanh(v);
            if (res) v += res[(size_t)row * Nc + col];
            C[(size_t)row * Nc + col] = v;
        }
    }
}

// ---------------- main attention: block per (b,head), 512 threads (one q row each)
__global__ void attn_kernel(const float* __restrict__ q, const float* __restrict__ k,
                            const float* __restrict__ v, const int* __restrict__ mask,
                            float* __restrict__ o) {
    __shared__ float ks[64][33];
    __shared__ float vs[64][33];
    int b = blockIdx.x >> 2, h = blockIdx.x & 3;
    int qi = threadIdx.x;
    float qr[DD];
    const float* qp = q + ((size_t)b * SS + qi) * HH + h * DD;
    #pragma unroll
    for (int d = 0; d < DD; d++) qr[d] = qp[d];
    float m = -1e30f, l = 0.0f;
    float acc[DD];
    #pragma unroll
    for (int d = 0; d < DD; d++) acc[d] = 0.0f;
    const int* mrow = mask + (size_t)b * SS * SS + (size_t)qi * SS;
    const float* kb = k + (size_t)b * SS * HH + h * DD;
    const float* vb = v + (size_t)b * SS * HH + h * DD;
    for (int c0 = 0; c0 < SS; c0 += 64) {
        __syncthreads();
        for (int idx = threadIdx.x; idx < 64 * DD; idx += 512) {
            int j = idx >> 5, d = idx & 31;
            ks[j][d] = kb[(size_t)(c0 + j) * HH + d];
            vs[j][d] = vb[(size_t)(c0 + j) * HH + d];
        }
        __syncthreads();
        #pragma unroll 4
        for (int j = 0; j < 64; j++) {
            float s = 0.0f;
            #pragma unroll
            for (int d = 0; d < DD; d++) s += qr[d] * ks[j][d];
            s *= 0.17677669529663687f;
            if (mrow[c0 + j] == 0) s = -1e9f;
            if (s <= m) {
                float p = __expf(s - m);
                l += p;
                #pragma unroll
                for (int d = 0; d < DD; d++) acc[d] += p * vs[j][d];
            } else {
                float corr = __expf(m - s);
                l = l * corr + 1.0f;
                #pragma unroll
                for (int d = 0; d < DD; d++) acc[d] = acc[d] * corr + vs[j][d];
                m = s;
            }
        }
    }
    float inv = 1.0f / l;
    float* op = o + ((size_t)b * SS + qi) * HH + h * DD;
    #pragma unroll
    for (int d = 0; d < DD; d++) op[d] = acc[d] * inv;
}

// ---------------- neighbor proj helper: out[64][129] = ln@W + bias -------------
__device__ __forceinline__ void proj64(const float* ln, const float* __restrict__ W,
                                       const float* __restrict__ bias, float* out, int tid) {
    int c2 = (tid & 63) * 2;
    int q4 = tid >> 6;
    int r0 = q4 * 16;
    float acc0[16], acc1[16];
    float bv0 = bias[c2], bv1 = bias[c2 + 1];
    #pragma unroll
    for (int i = 0; i < 16; i++) { acc0[i] = bv0; acc1[i] = bv1; }
    #pragma unroll 4
    for (int hh = 0; hh < HH; hh++) {
        float2 w = *(const float2*)&W[hh * HH + c2];
        #pragma unroll
        for (int i = 0; i < 16; i++) {
            float a = ln[(r0 + i) * 129 + hh];
            acc0[i] += a * w.x;
            acc1[i] += a * w.y;
        }
    }
    #pragma unroll
    for (int i = 0; i < 16; i++) {
        out[(r0 + i) * 129 + c2] = acc0[i];
        out[(r0 + i) * 129 + c2 + 1] = acc1[i];
    }
}

// ---------------- neighbor attention (last-token only): block per (n,b), 256 thr
__global__ void neigh_kernel(const float* __restrict__ neighs, const int* __restrict__ nmask,
                             const float* __restrict__ wq, const float* __restrict__ bq,
                             const float* __restrict__ wk, const float* __restrict__ bk,
                             const float* __restrict__ wv, const float* __restrict__ bv,
                             const float* __restrict__ wo, const float* __restrict__ bo,
                             const float* __restrict__ g1, const float* __restrict__ b1,
                             float* __restrict__ xnei) {
    extern __shared__ float sh[];
    float* ln  = sh;                 // 64*129
    float* kv  = ln + 64 * 129;      // 64*129
    float* qv  = kv + 64 * 129;      // 128
    float* osh = qv + 128;           // 128
    float* sc  = osh + 128;          // 4*64
    int tid = threadIdx.x;
    int nb = blockIdx.x;
    int n = nb / BB, b = nb % BB;
    const float* base = neighs + (size_t)nb * SNN * HH;
    // load tile
    for (int idx = tid; idx < SNN * HH; idx += 256) {
        int r = idx >> 7, c = idx & 127;
        ln[r * 129 + c] = base[idx];
    }
    __syncthreads();
    // layernorm rows (warp-per-row-group)
    {
        int warp = tid >> 5, lane = tid & 31;
        for (int r = warp; r < SNN; r += 8) {
            float s = 0.0f, s2 = 0.0f;
            #pragma unroll
            for (int c = lane; c < HH; c += 32) {
                float v = ln[r * 129 + c];
                s += v; s2 += v * v;
            }
            #pragma unroll
            for (int o = 16; o > 0; o >>= 1) {
                s  += __shfl_xor_sync(0xffffffffu, s, o);
                s2 += __shfl_xor_sync(0xffffffffu, s2, o);
            }
            float mean = s * (1.0f / HH);
            float var = s2 * (1.0f / HH) - mean * mean;
            float rs = rsqrtf(var + 1e-6f);
            #pragma unroll
            for (int c = lane; c < HH; c += 32) {
                float v = ln[r * 129 + c];
                ln[r * 129 + c] = (v - mean) * rs * g1[c] + b1[c];
            }
        }
    }
    __syncthreads();
    // K projection
    proj64(ln, wk, bk, kv, tid);
    // Q projection (last row only)
    if (tid < HH) {
        float a = bq[tid];
        #pragma unroll 4
        for (int hh = 0; hh < HH; hh++) a += ln[63 * 129 + hh] * wq[hh * HH + tid];
        qv[tid] = a;
    }
    __syncthreads();
    // scores
    {
        int head = tid >> 6, j = tid & 63;
        float s = 0.0f;
        #pragma unroll
        for (int d = 0; d < DD; d++) s += qv[head * DD + d] * kv[j * 129 + head * DD + d];
        s *= 0.17677669529663687f;
        int mval = nmask[((size_t)nb * SNN + (SNN - 1)) * SNN + j];
        if (mval == 0) s = -1e9f;
        sc[head * 64 + j] = s;
    }
    __syncthreads();
    if (tid < 4) {
        float m = -1e30f;
        for (int j = 0; j < 64; j++) m = fmaxf(m, sc[tid * 64 + j]);
        float l = 0.0f;
        for (int j = 0; j < 64; j++) {
            float p = __expf(sc[tid * 64 + j] - m);
            sc[tid * 64 + j] = p; l += p;
        }
        float inv = 1.0f / l;
        for (int j = 0; j < 64; j++) sc[tid * 64 + j] *= inv;
    }
    __syncthreads();
    // V projection (overwrite kv)
    proj64(ln, wv, bv, kv, tid);
    __syncthreads();
    // o = p @ v
    if (tid < HH) {
        int head = tid >> 5;
        float o = 0.0f;
        #pragma unroll 4
        for (int j = 0; j < 64; j++) o += sc[head * 64 + j] * kv[j * 129 + tid];
        osh[tid] = o;
    }
    __syncthreads();
    // out = residual + o @ wo + bo
    if (tid < HH) {
        float r = bo[tid] + base[(SNN - 1) * HH + tid];
        #pragma unroll 4
        for (int hh = 0; hh < HH; hh++) r += osh[hh] * wo[hh * HH + tid];
        xnei[((size_t)b * NN + n) * HH + tid] = r;
    }
}

// ---------------- attention-pooling kernel --------------------------------
// grid (8 s-tiles, 32 b), 256 threads; computes logits = relu(A + Bn + (x∘ne)@W2)·w2,
// softmax over n, out = x2 + att @ x_nei
__global__ void au_kernel(const float* __restrict__ x2, const float* __restrict__ Ag,
                          const float* __restrict__ Bng, const float* __restrict__ xnei,
                          const float* __restrict__ au_w1, const float* __restrict__ au_w2,
                          const float* __restrict__ au_b2, float* __restrict__ out) {
    extern __shared__ float sh[];
    float* W2s    = sh;               // 16384
    float* xs     = W2s + 16384;      // 64*132
    float* xns    = xs + 64 * 132;    // 16*128
    float* logits = xns + 2048;       // 64*17
    float* lpart  = logits + 64 * 17; // 64*16
    float* w2v    = lpart + 1024;     // 128
    int tid = threadIdx.x;
    int b = blockIdx.y;
    int s0 = blockIdx.x * 64;
    int tr = tid >> 4, tc = tid & 15;
    for (int idx = tid; idx < HH * HH; idx += 256) W2s[idx] = au_w1[HH * HH + idx];
    for (int idx = tid; idx < NN * HH; idx += 256) xns[idx] = xnei[(size_t)b * NN * HH + idx];
    if (tid < HH) w2v[tid] = au_w2[tid];
    __syncthreads();
    float bias2 = au_b2[0];
    for (int n = 0; n < NN; n++) {
        for (int idx = tid; idx < 64 * HH; idx += 256) {
            int r = idx >> 7, c = idx & 127;
            xs[r * 132 + c] = x2[((size_t)b * SS + s0 + r) * HH + c] * xns[n * HH + c];
        }
        __syncthreads();
        float acc[4][8] = {};
        #pragma unroll 2
        for (int hh = 0; hh < HH; hh++) {
            float a0 = xs[(tr * 4 + 0) * 132 + hh];
            float a1 = xs[(tr * 4 + 1) * 132 + hh];
            float a2 = xs[(tr * 4 + 2) * 132 + hh];
            float a3 = xs[(tr * 4 + 3) * 132 + hh];
            float4 w0 = *(float4*)&W2s[hh * HH + tc * 8];
            float4 w1 = *(float4*)&W2s[hh * HH + tc * 8 + 4];
            acc[0][0] += a0 * w0.x; acc[0][1] += a0 * w0.y; acc[0][2] += a0 * w0.z; acc[0][3] += a0 * w0.w;
            acc[0][4] += a0 * w1.x; acc[0][5] += a0 * w1.y; acc[0][6] += a0 * w1.z; acc[0][7] += a0 * w1.w;
            acc[1][0] += a1 * w0.x; acc[1][1] += a1 * w0.y; acc[1][2] += a1 * w0.z; acc[1][3] += a1 * w0.w;
            acc[1][4] += a1 * w1.x; acc[1][5] += a1 * w1.y; acc[1][6] += a1 * w1.z; acc[1][7] += a1 * w1.w;
            acc[2][0] += a2 * w0.x; acc[2][1] += a2 * w0.y; acc[2][2] += a2 * w0.z; acc[2][3] += a2 * w0.w;
            acc[2][4] += a2 * w1.x; acc[2][5] += a2 * w1.y; acc[2][6] += a2 * w1.z; acc[2][7] += a2 * w1.w;
            acc[3][0] += a3 * w0.x; acc[3][1] += a3 * w0.y; acc[3][2] += a3 * w0.z; acc[3][3] += a3 * w0.w;
            acc[3][4] += a3 * w1.x; acc[3][5] += a3 * w1.y; acc[3][6] += a3 * w1.z; acc[3][7] += a3 * w1.w;
        }
        float4 Bn0 = *(const float4*)&Bng[((size_t)b * NN + n) * HH + tc * 8];
        float4 Bn1 = *(const float4*)&Bng[((size_t)b * NN + n) * HH + tc * 8 + 4];
        float w2a[8];
        #pragma unroll
        for (int j = 0; j < 8; j++) w2a[j] = w2v[tc * 8 + j];
        #pragma unroll
        for (int i = 0; i < 4; i++) {
            int r = tr * 4 + i;
            size_t gb = ((size_t)b * SS + s0 + r) * HH + tc * 8;
            float4 A0 = *(const float4*)&Ag[gb];
            float4 A1 = *(const float4*)&Ag[gb + 4];
            float p = 0.0f;
            float vv;
            vv = acc[i][0] + A0.x + Bn0.x; vv = fmaxf(vv, 0.0f); p += vv * w2a[0];
            vv = acc[i][1] + A0.y + Bn0.y; vv = fmaxf(vv, 0.0f); p += vv * w2a[1];
            vv = acc[i][2] + A0.z + Bn0.z; vv = fmaxf(vv, 0.0f); p += vv * w2a[2];
            vv = acc[i][3] + A0.w + Bn0.w; vv = fmaxf(vv, 0.0f); p += vv * w2a[3];
            vv = acc[i][4] + A1.x + Bn1.x; vv = fmaxf(vv, 0.0f); p += vv * w2a[4];
            vv = acc[i][5] + A1.y + Bn1.y; vv = fmaxf(vv, 0.0f); p += vv * w2a[5];
            vv = acc[i][6] + A1.z + Bn1.z; vv = fmaxf(vv, 0.0f); p += vv * w2a[6];
            vv = acc[i][7] + A1.w + Bn1.w; vv = fmaxf(vv, 0.0f); p += vv * w2a[7];
            lpart[r * 16 + tc] = p;
        }
        __syncthreads();
        if (tid < 64) {
            float s = 0.0f;
            #pragma unroll
            for (int t = 0; t < 16; t++) s += lpart[tid * 16 + t];
            logits[tid * 17 + n] = s + bias2;
        }
        __syncthreads();
    }
    if (tid < 64) {
        float m = -1e30f;
        #pragma unroll
        for (int n = 0; n < NN; n++) m = fmaxf(m, logits[tid * 17 + n]);
        float l = 0.0f;
        #pragma unroll
        for (int n = 0; n < NN; n++) {
            float p = __expf(logits[tid * 17 + n] - m);
            logits[tid * 17 + n] = p; l += p;
        }
        float inv = 1.0f / l;
        #pragma unroll
        for (int n = 0; n < NN; n++) logits[tid * 17 + n] *= inv;
    }
    __syncthreads();
    for (int idx = tid; idx < 64 * HH; idx += 256) {
        int r = idx >> 7, c = idx & 127;
        float o = x2[((size_t)b * SS + s0 + r) * HH + c];
        #pragma unroll
        for (int n = 0; n < NN; n++) o += logits[r * 17 + n] * xns[n * HH + c];
        out[((size_t)b * SS + s0 + r) * HH + c] = o;
    }
}

// ---------------- launch ----------------
extern "C" void kernel_launch(void* const* d_in, const int* in_sizes, int n_in,
                              void* d_out, int out_size) {
    const float* x      = (const float*)d_in[0];
    const int*   mask   = (const int*)  d_in[1];
    const float* neighs = (const float*)d_in[2];
    const int*   nmask  = (const int*)  d_in[3];
    const float* wq = (const float*)d_in[4];  const float* bq = (const float*)d_in[5];
    const float* wk = (const float*)d_in[6];  const float* bk = (const float*)d_in[7];
    const float* wv = (const float*)d_in[8];  const float* bv = (const float*)d_in[9];
    const float* wo = (const float*)d_in[10]; const float* bo = (const float*)d_in[11];
    const float* ln1_g = (const float*)d_in[12]; const float* ln1_b = (const float*)d_in[13];
    const float* ln2_g = (const float*)d_in[14]; const float* ln2_b = (const float*)d_in[15];
    const float* ff_w1 = (const float*)d_in[16]; const float* ff_b1 = (const float*)d_in[17];
    const float* ff_w2 = (const float*)d_in[18]; const float* ff_b2 = (const float*)d_in[19];
    const float* au_w1 = (const float*)d_in[20]; const float* au_b1 = (const float*)d_in[21];
    const float* au_w2 = (const float*)d_in[22]; const float* au_b2 = (const float*)d_in[23];
    float* out = (float*)d_out;

    float *p_xn, *p_q, *p_k, *p_v, *p_attn, *p_x1, *p_h, *p_ffh, *p_x2, *p_A,
          *p_xnei, *p_Bn, *p_Wd, *p_Wnc;
    cudaGetSymbolAddress((void**)&p_xn, g_xn);
    cudaGetSymbolAddress((void**)&p_q, g_q);
    cudaGetSymbolAddress((void**)&p_k, g_k);
    cudaGetSymbolAddress((void**)&p_v, g_v);
    cudaGetSymbolAddress((void**)&p_attn, g_attn);
    cudaGetSymbolAddress((void**)&p_x1, g_x1);
    cudaGetSymbolAddress((void**)&p_h, g_h);
    cudaGetSymbolAddress((void**)&p_ffh, g_ffh);
    cudaGetSymbolAddress((void**)&p_x2, g_x2);
    cudaGetSymbolAddress((void**)&p_A, g_A);
    cudaGetSymbolAddress((void**)&p_xnei, g_xnei);
    cudaGetSymbolAddress((void**)&p_Bn, g_Bn);
    cudaGetSymbolAddress((void**)&p_Wd, g_Wd);
    cudaGetSymbolAddress((void**)&p_Wnc, g_Wnc);

    const int neigh_shmem = (64 * 129 * 2 + 128 + 128 + 256) * 4;              // ~68 KB
    const int au_shmem = (16384 + 64 * 132 + 2048 + 64 * 17 + 1024 + 128) * 4; // ~116 KB
    cudaFuncSetAttribute(neigh_kernel, cudaFuncAttributeMaxDynamicSharedMemorySize, neigh_shmem);
    cudaFuncSetAttribute(au_kernel, cudaFuncAttributeMaxDynamicSharedMemorySize, au_shmem);

    // au weight combine
    prep_au_kernel<<<32, 512>>>(au_w1, p_Wd, p_Wnc);
    // LN1
    ln_kernel<<<ROWS, 128>>>(x, ln1_g, ln1_b, p_xn);
    // QKV projections
    dim3 g128(HH / GBN, ROWS / GBM);
    sgemm_kernel<<<g128, 256>>>(p_xn, wq, bq, nullptr, p_q, ROWS, HH, HH, 0);
    sgemm_kernel<<<g128, 256>>>(p_xn, wk, bk, nullptr, p_k, ROWS, HH, HH, 0);
    sgemm_kernel<<<g128, 256>>>(p_xn, wv, bv, nullptr, p_v, ROWS, HH, HH, 0);
    // attention
    attn_kernel<<<BB * NHEADS, 512>>>(p_q, p_k, p_v, mask, p_attn);
    // output projection + residual
    sgemm_kernel<<<g128, 256>>>(p_attn, wo, bo, x, p_x1, ROWS, HH, HH, 0);
    // neighbor attention (independent branch)
    neigh_kernel<<<NN * BB, 256, neigh_shmem>>>(neighs, nmask, wq, bq, wk, bk, wv, bv,
                                                wo, bo, ln1_g, ln1_b, p_xnei);
    // LN2 + FF
    ln_kernel<<<ROWS, 128>>>(p_x1, ln2_g, ln2_b, p_h);
    dim3 gff1(FFD / GBN, ROWS / GBM);
    sgemm_kernel<<<gff1, 256>>>(p_h, ff_w1, ff_b1, nullptr, p_ffh, ROWS, HH, FFD, 1);
    sgemm_kernel<<<g128, 256>>>(p_ffh, ff_w2, ff_b2, p_x1, p_x2, ROWS, FFD, HH, 0);
    // au precomputes: A = x2@(W1-W3)+b1 ; Bn = xnei@(W3+W4)
    sgemm_kernel<<<g128, 256>>>(p_x2, p_Wd, au_b1, nullptr, p_A, ROWS, HH, HH, 0);
    dim3 gbn(HH / GBN, (BB * NN) / GBM);
    sgemm_kernel<<<gbn, 256>>>(p_xnei, p_Wnc, nullptr, nullptr, p_Bn, BB * NN, HH, HH, 0);
    // final attention-pooling
    dim3 gau(SS / 64, BB);
    au_kernel<<<gau, 256, au_shmem>>>(p_x2, p_A, p_Bn, p_xnei, au_w1, au_w2, au_b2, out);
}

// round 2
// speedup vs baseline: 1.0157x; 1.0157x over previous
#include <cuda_runtime.h>
#include <cuda_bf16.h>
#include <math.h>

// Problem dims
#define BB 32
#define SS 512
#define HH 128
#define NHEADS 4
#define DD 32
#define FFD 512
#define NN 16
#define SNN 64
#define ROWS (BB*SS)          // 16384

// ---------------- static device scratch ----------------
__device__ float g_xn  [ROWS*HH];
__device__ float g_qkv [ROWS*384];
__device__ float g_attn[ROWS*HH];
__device__ float g_x1  [ROWS*HH];
__device__ float g_h   [ROWS*HH];
__device__ float g_ffh [ROWS*FFD];
__device__ float g_x2  [ROWS*HH];
__device__ float g_A   [ROWS*HH];
__device__ float g_xnei[BB*NN*HH];
__device__ float g_Bn  [BB*NN*HH];
__device__ float g_Wd  [HH*HH];
__device__ float g_Wnc [HH*HH];
__device__ float g_Wqkv[HH*384];
__device__ float g_bqkv[384];

// ---------------- helpers ----------------
__device__ __forceinline__ float gelu_tanh(float x) {
    float t = tanhf(0.7978845608028654f * (x + 0.044715f * x * x * x));
    return 0.5f * x * (1.0f + t);
}

// ---------------- prep: Wd = W1-W3, Wnc = W3+W4, pack Wqkv/bqkv --------------
__global__ void prep_kernel(const float* __restrict__ au_w1,
                            const float* __restrict__ wq, const float* __restrict__ wk,
                            const float* __restrict__ wv,
                            const float* __restrict__ bq, const float* __restrict__ bk,
                            const float* __restrict__ bv,
                            float* __restrict__ Wd, float* __restrict__ Wnc,
                            float* __restrict__ Wqkv, float* __restrict__ bqkv) {
    int idx = blockIdx.x * blockDim.x + threadIdx.x;
    if (idx < HH * HH) {
        int h = idx >> 7, j = idx & 127;
        float w1 = au_w1[h * HH + j];
        float w3 = au_w1[(256 + h) * HH + j];
        float w4 = au_w1[(384 + h) * HH + j];
        Wd[idx]  = w1 - w3;
        Wnc[idx] = w3 + w4;
    }
    if (idx < HH * 384) {
        int h = idx / 384, c = idx % 384;
        float v = (c < 128) ? wq[h * 128 + c]
                 : (c < 256) ? wk[h * 128 + (c - 128)]
                             : wv[h * 128 + (c - 256)];
        Wqkv[idx] = v;
    }
    if (idx < 384) {
        bqkv[idx] = (idx < 128) ? bq[idx] : (idx < 256) ? bk[idx - 128] : bv[idx - 256];
    }
}

// ---------------- layernorm: one block per row, 128 threads ----------------
__global__ void ln_kernel(const float* __restrict__ x, const float* __restrict__ g,
                          const float* __restrict__ b, float* __restrict__ y) {
    int row = blockIdx.x;
    int t = threadIdx.x;
    float v = x[(size_t)row * HH + t];
    float s = v, s2 = v * v;
    #pragma unroll
    for (int o = 16; o > 0; o >>= 1) {
        s  += __shfl_xor_sync(0xffffffffu, s, o);
        s2 += __shfl_xor_sync(0xffffffffu, s2, o);
    }
    __shared__ float ws[8];
    if ((t & 31) == 0) { ws[t >> 5] = s; ws[4 + (t >> 5)] = s2; }
    __syncthreads();
    s  = ws[0] + ws[1] + ws[2] + ws[3];
    s2 = ws[4] + ws[5] + ws[6] + ws[7];
    float mean = s * (1.0f / HH);
    float var = s2 * (1.0f / HH) - mean * mean;
    float rs = rsqrtf(var + 1e-6f);
    y[(size_t)row * HH + t] = (v - mean) * rs * g[t] + b[t];
}

// ---------------- 128x128x16 SGEMM, double buffered, 8x8 microtile ----------
#define TBM 128
#define TBN 128
#define TBK 16
__global__ __launch_bounds__(256) void sgemm128(
    const float* __restrict__ A, const float* __restrict__ W,
    const float* __restrict__ bias, const float* __restrict__ res,
    float* __restrict__ C, int M, int K, int N, int act) {
    __shared__ float As[2][TBK][TBM];
    __shared__ float Ws[2][TBK][TBN];
    int bm = blockIdx.y * TBM, bn = blockIdx.x * TBN;
    int tid = threadIdx.x;
    int ty = tid >> 4, tx = tid & 15;
    int arow[2], ac4[2], wrow[2], wc4[2];
    #pragma unroll
    for (int l = 0; l < 2; l++) {
        int L = l * 256 + tid;
        arow[l] = L >> 2;  ac4[l] = L & 3;
        wrow[l] = L >> 5;  wc4[l] = L & 31;
    }
    float4 aL[2], wL[2];
    // prologue: tile 0
    #pragma unroll
    for (int l = 0; l < 2; l++) {
        aL[l] = *(const float4*)&A[(size_t)(bm + arow[l]) * K + ac4[l] * 4];
        wL[l] = *(const float4*)&W[(size_t)wrow[l] * N + bn + wc4[l] * 4];
    }
    #pragma unroll
    for (int l = 0; l < 2; l++) {
        As[0][ac4[l] * 4 + 0][arow[l]] = aL[l].x;
        As[0][ac4[l] * 4 + 1][arow[l]] = aL[l].y;
        As[0][ac4[l] * 4 + 2][arow[l]] = aL[l].z;
        As[0][ac4[l] * 4 + 3][arow[l]] = aL[l].w;
        *(float4*)&Ws[0][wrow[l]][wc4[l] * 4] = wL[l];
    }
    __syncthreads();
    float acc[8][8] = {};
    int nk = K / TBK;
    for (int kt = 0; kt < nk; kt++) {
        int cur = kt & 1;
        if (kt + 1 < nk) {
            int k0 = (kt + 1) * TBK;
            #pragma unroll
            for (int l = 0; l < 2; l++) {
                aL[l] = *(const float4*)&A[(size_t)(bm + arow[l]) * K + k0 + ac4[l] * 4];
                wL[l] = *(const float4*)&W[(size_t)(k0 + wrow[l]) * N + bn + wc4[l] * 4];
            }
        }
        #pragma unroll
        for (int kk = 0; kk < TBK; kk++) {
            float ar[8], br[8];
            *(float4*)&ar[0] = *(float4*)&As[cur][kk][ty * 8];
            *(float4*)&ar[4] = *(float4*)&As[cur][kk][ty * 8 + 4];
            *(float4*)&br[0] = *(float4*)&Ws[cur][kk][tx * 8];
            *(float4*)&br[4] = *(float4*)&Ws[cur][kk][tx * 8 + 4];
            #pragma unroll
            for (int i = 0; i < 8; i++)
                #pragma unroll
                for (int j = 0; j < 8; j++)
                    acc[i][j] += ar[i] * br[j];
        }
        if (kt + 1 < nk) {
            int nxt = cur ^ 1;
            #pragma unroll
            for (int l = 0; l < 2; l++) {
                As[nxt][ac4[l] * 4 + 0][arow[l]] = aL[l].x;
                As[nxt][ac4[l] * 4 + 1][arow[l]] = aL[l].y;
                As[nxt][ac4[l] * 4 + 2][arow[l]] = aL[l].z;
                As[nxt][ac4[l] * 4 + 3][arow[l]] = aL[l].w;
                *(float4*)&Ws[nxt][wrow[l]][wc4[l] * 4] = wL[l];
            }
        }
        __syncthreads();
    }
    // epilogue
    #pragma unroll
    for (int i = 0; i < 8; i++) {
        int row = bm + ty * 8 + i;
        #pragma unroll
        for (int jj = 0; jj < 2; jj++) {
            int col = bn + tx * 8 + jj * 4;
            float4 v;
            v.x = acc[i][jj * 4 + 0]; v.y = acc[i][jj * 4 + 1];
            v.z = acc[i][jj * 4 + 2]; v.w = acc[i][jj * 4 + 3];
            if (bias) {
                const float4 bv = *(const float4*)&bias[col];
                v.x += bv.x; v.y += bv.y; v.z += bv.z; v.w += bv.w;
            }
            if (act == 1) {
                v.x = gelu_tanh(v.x); v.y = gelu_tanh(v.y);
                v.z = gelu_tanh(v.z); v.w = gelu_tanh(v.w);
            }
            if (res) {
                const float4 rv = *(const float4*)&res[(size_t)row * N + col];
                v.x += rv.x; v.y += rv.y; v.z += rv.z; v.w += rv.w;
            }
            *(float4*)&C[(size_t)row * N + col] = v;
        }
    }
}

// ---------------- main attention: 256 blocks, 256 threads (one q row each) ---
__global__ __launch_bounds__(256) void attn_kernel(const float* __restrict__ qkv,
                                                   const int* __restrict__ mask,
                                                   float* __restrict__ o) {
    __shared__ float ks[64][33];
    __shared__ float vs[64][33];
    int blk = blockIdx.x;
    int b = blk >> 3, h = (blk >> 1) & 3, half = blk & 1;
    int qi = half * 256 + threadIdx.x;
    float qr[DD];
    const float* qp = qkv + ((size_t)(b * SS + qi)) * 384 + h * DD;
    #pragma unroll
    for (int d = 0; d < DD; d++) qr[d] = qp[d];
    float m = -1e30f, l = 0.0f;
    float acc[DD];
    #pragma unroll
    for (int d = 0; d < DD; d++) acc[d] = 0.0f;
    const int* mrow = mask + (size_t)b * SS * SS + (size_t)qi * SS;
    const float* kb = qkv + (size_t)b * SS * 384 + 128 + h * DD;
    const float* vb = qkv + (size_t)b * SS * 384 + 256 + h * DD;
    for (int c0 = 0; c0 < SS; c0 += 64) {
        __syncthreads();
        for (int idx = threadIdx.x; idx < 64 * DD; idx += 256) {
            int j = idx >> 5, d = idx & 31;
            ks[j][d] = kb[(size_t)(c0 + j) * 384 + d];
            vs[j][d] = vb[(size_t)(c0 + j) * 384 + d];
        }
        __syncthreads();
        #pragma unroll 4
        for (int j = 0; j < 64; j++) {
            float s = 0.0f;
            #pragma unroll
            for (int d = 0; d < DD; d++) s += qr[d] * ks[j][d];
            s *= 0.17677669529663687f;
            if (mrow[c0 + j] == 0) s = -1e9f;
            if (s <= m) {
                float p = __expf(s - m);
                l += p;
                #pragma unroll
                for (int d = 0; d < DD; d++) acc[d] += p * vs[j][d];
            } else {
                float corr = __expf(m - s);
                l = l * corr + 1.0f;
                #pragma unroll
                for (int d = 0; d < DD; d++) acc[d] = acc[d] * corr + vs[j][d];
                m = s;
            }
        }
    }
    float inv = 1.0f / l;
    float* op = o + ((size_t)b * SS + qi) * HH + h * DD;
    #pragma unroll
    for (int d = 0; d < DD; d++) op[d] = acc[d] * inv;
}

// ---------------- neighbor proj helper: out[64][129] = ln@W + bias -------------
__device__ __forceinline__ void proj64(const float* ln, const float* __restrict__ W,
                                       const float* __restrict__ bias, float* out, int tid) {
    int c2 = (tid & 63) * 2;
    int q4 = tid >> 6;
    int r0 = q4 * 16;
    float acc0[16], acc1[16];
    float bv0 = bias[c2], bv1 = bias[c2 + 1];
    #pragma unroll
    for (int i = 0; i < 16; i++) { acc0[i] = bv0; acc1[i] = bv1; }
    #pragma unroll 4
    for (int hh = 0; hh < HH; hh++) {
        float2 w = *(const float2*)&W[hh * HH + c2];
        #pragma unroll
        for (int i = 0; i < 16; i++) {
            float a = ln[(r0 + i) * 129 + hh];
            acc0[i] += a * w.x;
            acc1[i] += a * w.y;
        }
    }
    #pragma unroll
    for (int i = 0; i < 16; i++) {
        out[(r0 + i) * 129 + c2] = acc0[i];
        out[(r0 + i) * 129 + c2 + 1] = acc1[i];
    }
}

// ---------------- neighbor attention (last-token only): block per (n,b), 256 thr
__global__ void neigh_kernel(const float* __restrict__ neighs, const int* __restrict__ nmask,
                             const float* __restrict__ wq, const float* __restrict__ bq,
                             const float* __restrict__ wk, const float* __restrict__ bk,
                             const float* __restrict__ wv, const float* __restrict__ bv,
                             const float* __restrict__ wo, const float* __restrict__ bo,
                             const float* __restrict__ g1, const float* __restrict__ b1,
                             float* __restrict__ xnei) {
    extern __shared__ float sh[];
    float* ln  = sh;                 // 64*129
    float* kv  = ln + 64 * 129;      // 64*129
    float* qv  = kv + 64 * 129;      // 128
    float* osh = qv + 128;           // 128
    float* sc  = osh + 128;          // 4*64
    int tid = threadIdx.x;
    int nb = blockIdx.x;
    int n = nb / BB, b = nb % BB;
    const float* base = neighs + (size_t)nb * SNN * HH;
    for (int idx = tid; idx < SNN * HH; idx += 256) {
        int r = idx >> 7, c = idx & 127;
        ln[r * 129 + c] = base[idx];
    }
    __syncthreads();
    {
        int warp = tid >> 5, lane = tid & 31;
        for (int r = warp; r < SNN; r += 8) {
            float s = 0.0f, s2 = 0.0f;
            #pragma unroll
            for (int c = lane; c < HH; c += 32) {
                float v = ln[r * 129 + c];
                s += v; s2 += v * v;
            }
            #pragma unroll
            for (int o = 16; o > 0; o >>= 1) {
                s  += __shfl_xor_sync(0xffffffffu, s, o);
                s2 += __shfl_xor_sync(0xffffffffu, s2, o);
            }
            float mean = s * (1.0f / HH);
            float var = s2 * (1.0f / HH) - mean * mean;
            float rs = rsqrtf(var + 1e-6f);
            #pragma unroll
            for (int c = lane; c < HH; c += 32) {
                float v = ln[r * 129 + c];
                ln[r * 129 + c] = (v - mean) * rs * g1[c] + b1[c];
            }
        }
    }
    __syncthreads();
    proj64(ln, wk, bk, kv, tid);
    if (tid < HH) {
        float a = bq[tid];
        #pragma unroll 4
        for (int hh = 0; hh < HH; hh++) a += ln[63 * 129 + hh] * wq[hh * HH + tid];
        qv[tid] = a;
    }
    __syncthreads();
    {
        int head = tid >> 6, j = tid & 63;
        float s = 0.0f;
        #pragma unroll
        for (int d = 0; d < DD; d++) s += qv[head * DD + d] * kv[j * 129 + head * DD + d];
        s *= 0.17677669529663687f;
        int mval = nmask[((size_t)nb * SNN + (SNN - 1)) * SNN + j];
        if (mval == 0) s = -1e9f;
        sc[head * 64 + j] = s;
    }
    __syncthreads();
    if (tid < 4) {
        float m = -1e30f;
        for (int j = 0; j < 64; j++) m = fmaxf(m, sc[tid * 64 + j]);
        float l = 0.0f;
        for (int j = 0; j < 64; j++) {
            float p = __expf(sc[tid * 64 + j] - m);
            sc[tid * 64 + j] = p; l += p;
        }
        float inv = 1.0f / l;
        for (int j = 0; j < 64; j++) sc[tid * 64 + j] *= inv;
    }
    __syncthreads();
    proj64(ln, wv, bv, kv, tid);
    __syncthreads();
    if (tid < HH) {
        int head = tid >> 5;
        float o = 0.0f;
        #pragma unroll 4
        for (int j = 0; j < 64; j++) o += sc[head * 64 + j] * kv[j * 129 + tid];
        osh[tid] = o;
    }
    __syncthreads();
    if (tid < HH) {
        float r = bo[tid] + base[(SNN - 1) * HH + tid];
        #pragma unroll 4
        for (int hh = 0; hh < HH; hh++) r += osh[hh] * wo[hh * HH + tid];
        xnei[((size_t)b * NN + n) * HH + tid] = r;
    }
}

// ---------------- attention-pooling kernel --------------------------------
// grid (8 s-tiles, 32 b), 256 threads; logits = relu(A + Bn + (x∘ne)@W2)·w2,
// softmax over n, out = x2 + att @ x_nei.  A-tile held in registers.
__global__ __launch_bounds__(256) void au_kernel(
        const float* __restrict__ x2, const float* __restrict__ Ag,
        const float* __restrict__ Bng, const float* __restrict__ xnei,
        const float* __restrict__ au_w1, const float* __restrict__ au_w2,
        const float* __restrict__ au_b2, float* __restrict__ out) {
    extern __shared__ float sh[];
    float* W2s    = sh;                 // 16384
    float* xs     = W2s + 16384;        // 64*129 = 8256
    float* xns    = xs + 64 * 129;      // 16*128 = 2048
    float* logits = xns + 2048;         // 64*17  = 1088
    int tid = threadIdx.x;
    int b = blockIdx.y;
    int s0 = blockIdx.x * 64;
    int tr = tid >> 4, tc = tid & 15;
    for (int idx = tid; idx < HH * HH; idx += 256) W2s[idx] = au_w1[HH * HH + idx];
    for (int idx = tid; idx < NN * HH; idx += 256) xns[idx] = xnei[(size_t)b * NN * HH + idx];
    __syncthreads();
    // preload per-thread constants: A-tile fragment, w2 slice, bias
    float Areg[4][8];
    #pragma unroll
    for (int i = 0; i < 4; i++) {
        size_t gb = ((size_t)b * SS + s0 + tr * 4 + i) * HH + tc * 8;
        *(float4*)&Areg[i][0] = *(const float4*)&Ag[gb];
        *(float4*)&Areg[i][4] = *(const float4*)&Ag[gb + 4];
    }
    float w2a[8];
    *(float4*)&w2a[0] = *(const float4*)&au_w2[tc * 8];
    *(float4*)&w2a[4] = *(const float4*)&au_w2[tc * 8 + 4];
    float bias2 = au_b2[0];
    for (int n = 0; n < NN; n++) {
        for (int idx = tid; idx < 64 * HH; idx += 256) {
            int r = idx >> 7, c = idx & 127;
            xs[r * 129 + c] = x2[((size_t)b * SS + s0 + r) * HH + c] * xns[n * HH + c];
        }
        __syncthreads();
        float acc[4][8] = {};
        #pragma unroll 2
        for (int hh = 0; hh < HH; hh++) {
            float a0 = xs[(tr * 4 + 0) * 129 + hh];
            float a1 = xs[(tr * 4 + 1) * 129 + hh];
            float a2 = xs[(tr * 4 + 2) * 129 + hh];
            float a3 = xs[(tr * 4 + 3) * 129 + hh];
            float4 w0 = *(float4*)&W2s[hh * HH + tc * 8];
            float4 w1 = *(float4*)&W2s[hh * HH + tc * 8 + 4];
            acc[0][0] += a0 * w0.x; acc[0][1] += a0 * w0.y; acc[0][2] += a0 * w0.z; acc[0][3] += a0 * w0.w;
            acc[0][4] += a0 * w1.x; acc[0][5] += a0 * w1.y; acc[0][6] += a0 * w1.z; acc[0][7] += a0 * w1.w;
            acc[1][0] += a1 * w0.x; acc[1][1] += a1 * w0.y; acc[1][2] += a1 * w0.z; acc[1][3] += a1 * w0.w;
            acc[1][4] += a1 * w1.x; acc[1][5] += a1 * w1.y; acc[1][6] += a1 * w1.z; acc[1][7] += a1 * w1.w;
            acc[2][0] += a2 * w0.x; acc[2][1] += a2 * w0.y; acc[2][2] += a2 * w0.z; acc[2][3] += a2 * w0.w;
            acc[2][4] += a2 * w1.x; acc[2][5] += a2 * w1.y; acc[2][6] += a2 * w1.z; acc[2][7] += a2 * w1.w;
            acc[3][0] += a3 * w0.x; acc[3][1] += a3 * w0.y; acc[3][2] += a3 * w0.z; acc[3][3] += a3 * w0.w;
            acc[3][4] += a3 * w1.x; acc[3][5] += a3 * w1.y; acc[3][6] += a3 * w1.z; acc[3][7] += a3 * w1.w;
        }
        float Bn[8];
        size_t bb = ((size_t)b * NN + n) * HH + tc * 8;
        *(float4*)&Bn[0] = *(const float4*)&Bng[bb];
        *(float4*)&Bn[4] = *(const float4*)&Bng[bb + 4];
        #pragma unroll
        for (int i = 0; i < 4; i++) {
            float p = 0.0f;
            #pragma unroll
            for (int j = 0; j < 8; j++) {
                float vv = acc[i][j] + Areg[i][j] + Bn[j];
                vv = fmaxf(vv, 0.0f);
                p += vv * w2a[j];
            }
            // reduce over the 16 tc lanes (lanes tc + 16*(tr&1))
            #pragma unroll
            for (int o = 8; o > 0; o >>= 1) p += __shfl_xor_sync(0xffffffffu, p, o);
            if (tc == 0) logits[(tr * 4 + i) * 17 + n] = p + bias2;
        }
        __syncthreads();
    }
    if (tid < 64) {
        float m = -1e30f;
        #pragma unroll
        for (int n = 0; n < NN; n++) m = fmaxf(m, logits[tid * 17 + n]);
        float l = 0.0f;
        #pragma unroll
        for (int n = 0; n < NN; n++) {
            float p = __expf(logits[tid * 17 + n] - m);
            logits[tid * 17 + n] = p; l += p;
        }
        float inv = 1.0f / l;
        #pragma unroll
        for (int n = 0; n < NN; n++) logits[tid * 17 + n] *= inv;
    }
    __syncthreads();
    for (int idx = tid; idx < 64 * HH; idx += 256) {
        int r = idx >> 7, c = idx & 127;
        float o = x2[((size_t)b * SS + s0 + r) * HH + c];
        #pragma unroll
        for (int n = 0; n < NN; n++) o += logits[r * 17 + n] * xns[n * HH + c];
        out[((size_t)b * SS + s0 + r) * HH + c] = o;
    }
}

// ---------------- launch ----------------
extern "C" void kernel_launch(void* const* d_in, const int* in_sizes, int n_in,
                              void* d_out, int out_size) {
    const float* x      = (const float*)d_in[0];
    const int*   mask   = (const int*)  d_in[1];
    const float* neighs = (const float*)d_in[2];
    const int*   nmask  = (const int*)  d_in[3];
    const float* wq = (const float*)d_in[4];  const float* bq = (const float*)d_in[5];
    const float* wk = (const float*)d_in[6];  const float* bk = (const float*)d_in[7];
    const float* wv = (const float*)d_in[8];  const float* bv = (const float*)d_in[9];
    const float* wo = (const float*)d_in[10]; const float* bo = (const float*)d_in[11];
    const float* ln1_g = (const float*)d_in[12]; const float* ln1_b = (const float*)d_in[13];
    const float* ln2_g = (const float*)d_in[14]; const float* ln2_b = (const float*)d_in[15];
    const float* ff_w1 = (const float*)d_in[16]; const float* ff_b1 = (const float*)d_in[17];
    const float* ff_w2 = (const float*)d_in[18]; const float* ff_b2 = (const float*)d_in[19];
    const float* au_w1 = (const float*)d_in[20]; const float* au_b1 = (const float*)d_in[21];
    const float* au_w2 = (const float*)d_in[22]; const float* au_b2 = (const float*)d_in[23];
    float* out = (float*)d_out;

    float *p_xn, *p_qkv, *p_attn, *p_x1, *p_h, *p_ffh, *p_x2, *p_A,
          *p_xnei, *p_Bn, *p_Wd, *p_Wnc, *p_Wqkv, *p_bqkv;
    cudaGetSymbolAddress((void**)&p_xn, g_xn);
    cudaGetSymbolAddress((void**)&p_qkv, g_qkv);
    cudaGetSymbolAddress((void**)&p_attn, g_attn);
    cudaGetSymbolAddress((void**)&p_x1, g_x1);
    cudaGetSymbolAddress((void**)&p_h, g_h);
    cudaGetSymbolAddress((void**)&p_ffh, g_ffh);
    cudaGetSymbolAddress((void**)&p_x2, g_x2);
    cudaGetSymbolAddress((void**)&p_A, g_A);
    cudaGetSymbolAddress((void**)&p_xnei, g_xnei);
    cudaGetSymbolAddress((void**)&p_Bn, g_Bn);
    cudaGetSymbolAddress((void**)&p_Wd, g_Wd);
    cudaGetSymbolAddress((void**)&p_Wnc, g_Wnc);
    cudaGetSymbolAddress((void**)&p_Wqkv, g_Wqkv);
    cudaGetSymbolAddress((void**)&p_bqkv, g_bqkv);

    const int neigh_shmem = (64 * 129 * 2 + 128 + 128 + 256) * 4;            // ~68 KB
    const int au_shmem = (16384 + 64 * 129 + 2048 + 64 * 17) * 4;            // ~111 KB
    cudaFuncSetAttribute(neigh_kernel, cudaFuncAttributeMaxDynamicSharedMemorySize, neigh_shmem);
    cudaFuncSetAttribute(au_kernel, cudaFuncAttributeMaxDynamicSharedMemorySize, au_shmem);

    // weight prep (Wd/Wnc/Wqkv/bqkv)
    prep_kernel<<<192, 256>>>(au_w1, wq, wk, wv, bq, bk, bv, p_Wd, p_Wnc, p_Wqkv, p_bqkv);
    // LN1
    ln_kernel<<<ROWS, 128>>>(x, ln1_g, ln1_b, p_xn);
    // fused QKV projection: [16384,128] @ [128,384]
    {
        dim3 g(384 / TBN, ROWS / TBM);
        sgemm128<<<g, 256>>>(p_xn, p_Wqkv, p_bqkv, nullptr, p_qkv, ROWS, HH, 384, 0);
    }
    // attention
    attn_kernel<<<BB * NHEADS * 2, 256>>>(p_qkv, mask, p_attn);
    // output projection + residual
    {
        dim3 g(1, ROWS / TBM);
        sgemm128<<<g, 256>>>(p_attn, wo, bo, x, p_x1, ROWS, HH, HH, 0);
    }
    // neighbor attention (independent branch)
    neigh_kernel<<<NN * BB, 256, neigh_shmem>>>(neighs, nmask, wq, bq, wk, bk, wv, bv,
                                                wo, bo, ln1_g, ln1_b, p_xnei);
    // LN2 + FF
    ln_kernel<<<ROWS, 128>>>(p_x1, ln2_g, ln2_b, p_h);
    {
        dim3 g(FFD / TBN, ROWS / TBM);
        sgemm128<<<g, 256>>>(p_h, ff_w1, ff_b1, nullptr, p_ffh, ROWS, HH, FFD, 1);
    }
    {
        dim3 g(1, ROWS / TBM);
        sgemm128<<<g, 256>>>(p_ffh, ff_w2, ff_b2, p_x1, p_x2, ROWS, FFD, HH, 0);
    }
    // au precomputes: A = x2@(W1-W3)+b1 ; Bn = xnei@(W3+W4)
    {
        dim3 g(1, ROWS / TBM);
        sgemm128<<<g, 256>>>(p_x2, p_Wd, au_b1, nullptr, p_A, ROWS, HH, HH, 0);
    }
    {
        dim3 g(1, (BB * NN) / TBM);
        sgemm128<<<g, 256>>>(p_xnei, p_Wnc, nullptr, nullptr, p_Bn, BB * NN, HH, HH, 0);
    }
    // final attention-pooling
    {
        dim3 g(SS / 64, BB);
        au_kernel<<<g, 256, au_shmem>>>(p_x2, p_A, p_Bn, p_xnei, au_w1, au_w2, au_b2, out);
    }
}

// round 3
// speedup vs baseline: 1.1494x; 1.1317x over previous
#include <cuda_runtime.h>
#include <cuda_bf16.h>
#include <math.h>

// Problem dims
#define BB 32
#define SS 512
#define HH 128
#define NHEADS 4
#define DD 32
#define FFD 512
#define NN 16
#define SNN 64
#define ROWS (BB*SS)          // 16384

// ---------------- static device scratch ----------------
__device__ float g_xn  [ROWS*HH];
__device__ float g_qkv [ROWS*384];
__device__ float g_attn[ROWS*HH];
__device__ float g_x1  [ROWS*HH];
__device__ float g_h   [ROWS*HH];
__device__ float g_ffh [ROWS*FFD];
__device__ float g_x2  [ROWS*HH];
__device__ float g_A   [ROWS*HH];
__device__ float g_xnei[BB*NN*HH];
__device__ float g_Bn  [BB*NN*HH];
__device__ float g_Wd  [HH*HH];
__device__ float g_Wnc [HH*HH];
__device__ float g_Wqkv[HH*384];
__device__ float g_bqkv[384];

// ---------------- fast exp: FMA-pipe polynomial (no MUFU) ----------------
__device__ __forceinline__ float fast_exp(float x) {
    float z = x * 1.4426950408889634f;           // log2(e)
    z = fminf(fmaxf(z, -126.0f), 126.0f);
    float t = z + 12582912.0f;                   // 1.5*2^23 round trick
    int n = __float_as_int(t) - 0x4B400000;
    float f = z - (t - 12582912.0f);             // f in [-0.5, 0.5]
    float p = 0.0013333558f;
    p = fmaf(p, f, 0.0096181291f);
    p = fmaf(p, f, 0.0555041087f);
    p = fmaf(p, f, 0.2402265070f);
    p = fmaf(p, f, 0.6931471806f);
    p = fmaf(p, f, 1.0f);
    return __int_as_float(__float_as_int(p) + (n << 23));
}

// gelu(x) = x * sigmoid(2u), u = c(x + 0.044715 x^3)
__device__ __forceinline__ float gelu_fast(float x) {
    float u = 0.7978845608028654f * (x + 0.044715f * x * x * x);
    float t = fast_exp(-2.0f * u);
    return __fdividef(x, 1.0f + t);
}

// ---------------- prep: Wd = W1-W3, Wnc = W3+W4, pack Wqkv/bqkv --------------
__global__ void prep_kernel(const float* __restrict__ au_w1,
                            const float* __restrict__ wq, const float* __restrict__ wk,
                            const float* __restrict__ wv,
                            const float* __restrict__ bq, const float* __restrict__ bk,
                            const float* __restrict__ bv,
                            float* __restrict__ Wd, float* __restrict__ Wnc,
                            float* __restrict__ Wqkv, float* __restrict__ bqkv) {
    int idx = blockIdx.x * blockDim.x + threadIdx.x;
    if (idx < HH * HH) {
        int h = idx >> 7, j = idx & 127;
        float w1 = au_w1[h * HH + j];
        float w3 = au_w1[(256 + h) * HH + j];
        float w4 = au_w1[(384 + h) * HH + j];
        Wd[idx]  = w1 - w3;
        Wnc[idx] = w3 + w4;
    }
    if (idx < HH * 384) {
        int h = idx / 384, c = idx % 384;
        float v = (c < 128) ? wq[h * 128 + c]
                 : (c < 256) ? wk[h * 128 + (c - 128)]
                             : wv[h * 128 + (c - 256)];
        Wqkv[idx] = v;
    }
    if (idx < 384) {
        bqkv[idx] = (idx < 128) ? bq[idx] : (idx < 256) ? bk[idx - 128] : bv[idx - 256];
    }
}

// ---------------- layernorm: one block per row, 128 threads ----------------
__global__ void ln_kernel(const float* __restrict__ x, const float* __restrict__ g,
                          const float* __restrict__ b, float* __restrict__ y) {
    int row = blockIdx.x;
    int t = threadIdx.x;
    float v = x[(size_t)row * HH + t];
    float s = v, s2 = v * v;
    #pragma unroll
    for (int o = 16; o > 0; o >>= 1) {
        s  += __shfl_xor_sync(0xffffffffu, s, o);
        s2 += __shfl_xor_sync(0xffffffffu, s2, o);
    }
    __shared__ float ws[8];
    if ((t & 31) == 0) { ws[t >> 5] = s; ws[4 + (t >> 5)] = s2; }
    __syncthreads();
    s  = ws[0] + ws[1] + ws[2] + ws[3];
    s2 = ws[4] + ws[5] + ws[6] + ws[7];
    float mean = s * (1.0f / HH);
    float var = s2 * (1.0f / HH) - mean * mean;
    float rs = rsqrtf(var + 1e-6f);
    y[(size_t)row * HH + t] = (v - mean) * rs * g[t] + b[t];
}

// ---------------- 128x128x16 SGEMM, double buffered, 8x8 microtile ----------
#define TBM 128
#define TBN 128
#define TBK 16
__global__ __launch_bounds__(256) void sgemm128(
    const float* __restrict__ A, const float* __restrict__ W,
    const float* __restrict__ bias, const float* __restrict__ res,
    float* __restrict__ C, int M, int K, int N, int act) {
    __shared__ float As[2][TBK][TBM];
    __shared__ float Ws[2][TBK][TBN];
    int bm = blockIdx.y * TBM, bn = blockIdx.x * TBN;
    int tid = threadIdx.x;
    int ty = tid >> 4, tx = tid & 15;
    int arow[2], ac4[2], wrow[2], wc4[2];
    #pragma unroll
    for (int l = 0; l < 2; l++) {
        int L = l * 256 + tid;
        arow[l] = L >> 2;  ac4[l] = L & 3;
        wrow[l] = L >> 5;  wc4[l] = L & 31;
    }
    float4 aL[2], wL[2];
    #pragma unroll
    for (int l = 0; l < 2; l++) {
        aL[l] = *(const float4*)&A[(size_t)(bm + arow[l]) * K + ac4[l] * 4];
        wL[l] = *(const float4*)&W[(size_t)wrow[l] * N + bn + wc4[l] * 4];
    }
    #pragma unroll
    for (int l = 0; l < 2; l++) {
        As[0][ac4[l] * 4 + 0][arow[l]] = aL[l].x;
        As[0][ac4[l] * 4 + 1][arow[l]] = aL[l].y;
        As[0][ac4[l] * 4 + 2][arow[l]] = aL[l].z;
        As[0][ac4[l] * 4 + 3][arow[l]] = aL[l].w;
        *(float4*)&Ws[0][wrow[l]][wc4[l] * 4] = wL[l];
    }
    __syncthreads();
    float acc[8][8] = {};
    int nk = K / TBK;
    for (int kt = 0; kt < nk; kt++) {
        int cur = kt & 1;
        if (kt + 1 < nk) {
            int k0 = (kt + 1) * TBK;
            #pragma unroll
            for (int l = 0; l < 2; l++) {
                aL[l] = *(const float4*)&A[(size_t)(bm + arow[l]) * K + k0 + ac4[l] * 4];
                wL[l] = *(const float4*)&W[(size_t)(k0 + wrow[l]) * N + bn + wc4[l] * 4];
            }
        }
        #pragma unroll
        for (int kk = 0; kk < TBK; kk++) {
            float ar[8], br[8];
            *(float4*)&ar[0] = *(float4*)&As[cur][kk][ty * 8];
            *(float4*)&ar[4] = *(float4*)&As[cur][kk][ty * 8 + 4];
            *(float4*)&br[0] = *(float4*)&Ws[cur][kk][tx * 8];
            *(float4*)&br[4] = *(float4*)&Ws[cur][kk][tx * 8 + 4];
            #pragma unroll
            for (int i = 0; i < 8; i++)
                #pragma unroll
                for (int j = 0; j < 8; j++)
                    acc[i][j] += ar[i] * br[j];
        }
        if (kt + 1 < nk) {
            int nxt = cur ^ 1;
            #pragma unroll
            for (int l = 0; l < 2; l++) {
                As[nxt][ac4[l] * 4 + 0][arow[l]] = aL[l].x;
                As[nxt][ac4[l] * 4 + 1][arow[l]] = aL[l].y;
                As[nxt][ac4[l] * 4 + 2][arow[l]] = aL[l].z;
                As[nxt][ac4[l] * 4 + 3][arow[l]] = aL[l].w;
                *(float4*)&Ws[nxt][wrow[l]][wc4[l] * 4] = wL[l];
            }
        }
        __syncthreads();
    }
    #pragma unroll
    for (int i = 0; i < 8; i++) {
        int row = bm + ty * 8 + i;
        #pragma unroll
        for (int jj = 0; jj < 2; jj++) {
            int col = bn + tx * 8 + jj * 4;
            float4 v;
            v.x = acc[i][jj * 4 + 0]; v.y = acc[i][jj * 4 + 1];
            v.z = acc[i][jj * 4 + 2]; v.w = acc[i][jj * 4 + 3];
            if (bias) {
                const float4 bv = *(const float4*)&bias[col];
                v.x += bv.x; v.y += bv.y; v.z += bv.z; v.w += bv.w;
            }
            if (act == 1) {
                v.x = gelu_fast(v.x); v.y = gelu_fast(v.y);
                v.z = gelu_fast(v.z); v.w = gelu_fast(v.w);
            }
            if (res) {
                const float4 rv = *(const float4*)&res[(size_t)row * N + col];
                v.x += rv.x; v.y += rv.y; v.z += rv.z; v.w += rv.w;
            }
            *(float4*)&C[(size_t)row * N + col] = v;
        }
    }
}

// ---------------- tiled flash attention -----------------------------------
// block = (b, h, q-tile of 64 rows); 256 threads (16x16).
// S-frag 4x4 per thread (rows tr*4+i, cols tc+16j), O acc 4x2 (cols tc, tc+16).
__global__ __launch_bounds__(256) void attn_kernel(const float* __restrict__ qkv,
                                                   const int* __restrict__ mask,
                                                   float* __restrict__ o) {
    __shared__ float Qs[64][36];
    __shared__ float Ks[64][36];
    __shared__ float Vs[64][36];
    __shared__ float Ps[64][65];
    __shared__ float m_s[64];
    __shared__ float l_s[64];
    int blk = blockIdx.x;
    int qt = blk & 7, h = (blk >> 3) & 3, b = blk >> 5;
    int q0 = qt * 64;
    int tid = threadIdx.x;
    int tr = tid >> 4, tc = tid & 15;
    const float* qbase = qkv + (size_t)(b * SS + q0) * 384 + h * 32;
    // load Q tile
    #pragma unroll
    for (int k = 0; k < 2; k++) {
        int idx = tid + k * 256;           // 512 float4 = 64 rows x 8
        int r = idx >> 3, c4 = idx & 7;
        float4 v = *(const float4*)&qbase[(size_t)r * 384 + c4 * 4];
        *(float4*)&Qs[r][c4 * 4] = v;
    }
    if (tid < 64) { m_s[tid] = -1e30f; l_s[tid] = 0.0f; }
    float acc_o[4][2] = {};
    const int* mbase = mask + (size_t)b * SS * SS + (size_t)q0 * SS;
    const float* kbase = qkv + (size_t)b * SS * 384 + 128 + h * 32;
    const float* vbase = qkv + (size_t)b * SS * 384 + 256 + h * 32;
    for (int kt = 0; kt < 8; kt++) {
        int c0 = kt * 64;
        #pragma unroll
        for (int k = 0; k < 2; k++) {
            int idx = tid + k * 256;
            int r = idx >> 3, c4 = idx & 7;
            float4 kv4 = *(const float4*)&kbase[(size_t)(c0 + r) * 384 + c4 * 4];
            float4 vv4 = *(const float4*)&vbase[(size_t)(c0 + r) * 384 + c4 * 4];
            *(float4*)&Ks[r][c4 * 4] = kv4;
            *(float4*)&Vs[r][c4 * 4] = vv4;
        }
        __syncthreads();
        // S = Q @ K^T fragment
        float sacc[4][4] = {};
        #pragma unroll
        for (int d4 = 0; d4 < 8; d4++) {
            float4 qv[4], kv[4];
            #pragma unroll
            for (int i = 0; i < 4; i++) qv[i] = *(float4*)&Qs[tr * 4 + i][d4 * 4];
            #pragma unroll
            for (int j = 0; j < 4; j++) kv[j] = *(float4*)&Ks[tc + 16 * j][d4 * 4];
            #pragma unroll
            for (int i = 0; i < 4; i++)
                #pragma unroll
                for (int j = 0; j < 4; j++) {
                    sacc[i][j] += qv[i].x * kv[j].x;
                    sacc[i][j] += qv[i].y * kv[j].y;
                    sacc[i][j] += qv[i].z * kv[j].z;
                    sacc[i][j] += qv[i].w * kv[j].w;
                }
        }
        // online softmax per row
        #pragma unroll
        for (int i = 0; i < 4; i++) {
            int r = tr * 4 + i;
            const int* mrow = mbase + (size_t)r * SS + c0;
            float sv[4];
            #pragma unroll
            for (int j = 0; j < 4; j++) {
                float s = sacc[i][j] * 0.17677669529663687f;
                if (mrow[tc + 16 * j] == 0) s = -1e9f;
                sv[j] = s;
            }
            float tmax = fmaxf(fmaxf(sv[0], sv[1]), fmaxf(sv[2], sv[3]));
            #pragma unroll
            for (int off = 8; off > 0; off >>= 1)
                tmax = fmaxf(tmax, __shfl_xor_sync(0xffffffffu, tmax, off));
            float m_old = m_s[r];
            float m_new = fmaxf(m_old, tmax);
            float corr = fast_exp(m_old - m_new);
            float p0 = fast_exp(sv[0] - m_new);
            float p1 = fast_exp(sv[1] - m_new);
            float p2 = fast_exp(sv[2] - m_new);
            float p3 = fast_exp(sv[3] - m_new);
            float psum = (p0 + p1) + (p2 + p3);
            #pragma unroll
            for (int off = 8; off > 0; off >>= 1)
                psum += __shfl_xor_sync(0xffffffffu, psum, off);
            acc_o[i][0] *= corr;
            acc_o[i][1] *= corr;
            if (tc == 0) { m_s[r] = m_new; l_s[r] = l_s[r] * corr + psum; }
            Ps[r][tc]      = p0;
            Ps[r][tc + 16] = p1;
            Ps[r][tc + 32] = p2;
            Ps[r][tc + 48] = p3;
        }
        __syncthreads();
        // O += P @ V
        #pragma unroll 8
        for (int j = 0; j < 64; j++) {
            float b0 = Vs[j][tc];
            float b1 = Vs[j][tc + 16];
            #pragma unroll
            for (int i = 0; i < 4; i++) {
                float a = Ps[tr * 4 + i][j];
                acc_o[i][0] += a * b0;
                acc_o[i][1] += a * b1;
            }
        }
        __syncthreads();
    }
    // epilogue
    #pragma unroll
    for (int i = 0; i < 4; i++) {
        int r = tr * 4 + i;
        float inv = __fdividef(1.0f, l_s[r]);
        float* op = o + (size_t)(b * SS + q0 + r) * HH + h * 32;
        op[tc]      = acc_o[i][0] * inv;
        op[tc + 16] = acc_o[i][1] * inv;
    }
}

// ---------------- neighbor proj helper: out[64][129] = ln@W + bias -------------
__device__ __forceinline__ void proj64(const float* ln, const float* __restrict__ W,
                                       const float* __restrict__ bias, float* out, int tid) {
    int c2 = (tid & 63) * 2;
    int q4 = tid >> 6;
    int r0 = q4 * 16;
    float acc0[16], acc1[16];
    float bv0 = bias[c2], bv1 = bias[c2 + 1];
    #pragma unroll
    for (int i = 0; i < 16; i++) { acc0[i] = bv0; acc1[i] = bv1; }
    #pragma unroll 4
    for (int hh = 0; hh < HH; hh++) {
        float2 w = *(const float2*)&W[hh * HH + c2];
        #pragma unroll
        for (int i = 0; i < 16; i++) {
            float a = ln[(r0 + i) * 129 + hh];
            acc0[i] += a * w.x;
            acc1[i] += a * w.y;
        }
    }
    #pragma unroll
    for (int i = 0; i < 16; i++) {
        out[(r0 + i) * 129 + c2] = acc0[i];
        out[(r0 + i) * 129 + c2 + 1] = acc1[i];
    }
}

// ---------------- neighbor attention (last-token only): block per (n,b), 256 thr
__global__ void neigh_kernel(const float* __restrict__ neighs, const int* __restrict__ nmask,
                             const float* __restrict__ wq, const float* __restrict__ bq,
                             const float* __restrict__ wk, const float* __restrict__ bk,
                             const float* __restrict__ wv, const float* __restrict__ bv,
                             const float* __restrict__ wo, const float* __restrict__ bo,
                             const float* __restrict__ g1, const float* __restrict__ b1,
                             float* __restrict__ xnei) {
    extern __shared__ float sh[];
    float* ln  = sh;                 // 64*129
    float* kv  = ln + 64 * 129;      // 64*129
    float* qv  = kv + 64 * 129;      // 128
    float* osh = qv + 128;           // 128
    float* sc  = osh + 128;          // 4*64
    int tid = threadIdx.x;
    int nb = blockIdx.x;
    int n = nb / BB, b = nb % BB;
    const float* base = neighs + (size_t)nb * SNN * HH;
    for (int idx = tid; idx < SNN * HH; idx += 256) {
        int r = idx >> 7, c = idx & 127;
        ln[r * 129 + c] = base[idx];
    }
    __syncthreads();
    {
        int warp = tid >> 5, lane = tid & 31;
        for (int r = warp; r < SNN; r += 8) {
            float s = 0.0f, s2 = 0.0f;
            #pragma unroll
            for (int c = lane; c < HH; c += 32) {
                float v = ln[r * 129 + c];
                s += v; s2 += v * v;
            }
            #pragma unroll
            for (int o = 16; o > 0; o >>= 1) {
                s  += __shfl_xor_sync(0xffffffffu, s, o);
                s2 += __shfl_xor_sync(0xffffffffu, s2, o);
            }
            float mean = s * (1.0f / HH);
            float var = s2 * (1.0f / HH) - mean * mean;
            float rs = rsqrtf(var + 1e-6f);
            #pragma unroll
            for (int c = lane; c < HH; c += 32) {
                float v = ln[r * 129 + c];
                ln[r * 129 + c] = (v - mean) * rs * g1[c] + b1[c];
            }
        }
    }
    __syncthreads();
    proj64(ln, wk, bk, kv, tid);
    if (tid < HH) {
        float a = bq[tid];
        #pragma unroll 4
        for (int hh = 0; hh < HH; hh++) a += ln[63 * 129 + hh] * wq[hh * HH + tid];
        qv[tid] = a;
    }
    __syncthreads();
    {
        int head = tid >> 6, j = tid & 63;
        float s = 0.0f;
        #pragma unroll
        for (int d = 0; d < DD; d++) s += qv[head * DD + d] * kv[j * 129 + head * DD + d];
        s *= 0.17677669529663687f;
        int mval = nmask[((size_t)nb * SNN + (SNN - 1)) * SNN + j];
        if (mval == 0) s = -1e9f;
        sc[head * 64 + j] = s;
    }
    __syncthreads();
    if (tid < 4) {
        float m = -1e30f;
        for (int j = 0; j < 64; j++) m = fmaxf(m, sc[tid * 64 + j]);
        float l = 0.0f;
        for (int j = 0; j < 64; j++) {
            float p = fast_exp(sc[tid * 64 + j] - m);
            sc[tid * 64 + j] = p; l += p;
        }
        float inv = 1.0f / l;
        for (int j = 0; j < 64; j++) sc[tid * 64 + j] *= inv;
    }
    __syncthreads();
    proj64(ln, wv, bv, kv, tid);
    __syncthreads();
    if (tid < HH) {
        int head = tid >> 5;
        float o = 0.0f;
        #pragma unroll 4
        for (int j = 0; j < 64; j++) o += sc[head * 64 + j] * kv[j * 129 + tid];
        osh[tid] = o;
    }
    __syncthreads();
    if (tid < HH) {
        float r = bo[tid] + base[(SNN - 1) * HH + tid];
        #pragma unroll 4
        for (int hh = 0; hh < HH; hh++) r += osh[hh] * wo[hh * HH + tid];
        xnei[((size_t)b * NN + n) * HH + tid] = r;
    }
}

// ---------------- attention-pooling kernel --------------------------------
__global__ __launch_bounds__(256) void au_kernel(
        const float* __restrict__ x2, const float* __restrict__ Ag,
        const float* __restrict__ Bng, const float* __restrict__ xnei,
        const float* __restrict__ au_w1, const float* __restrict__ au_w2,
        const float* __restrict__ au_b2, float* __restrict__ out) {
    extern __shared__ float sh[];
    float* W2s    = sh;                 // 16384
    float* xs     = W2s + 16384;        // 64*129 = 8256
    float* xns    = xs + 64 * 129;      // 16*128 = 2048
    float* logits = xns + 2048;         // 64*17  = 1088
    int tid = threadIdx.x;
    int b = blockIdx.y;
    int s0 = blockIdx.x * 64;
    int tr = tid >> 4, tc = tid & 15;
    for (int idx = tid; idx < HH * HH; idx += 256) W2s[idx] = au_w1[HH * HH + idx];
    for (int idx = tid; idx < NN * HH; idx += 256) xns[idx] = xnei[(size_t)b * NN * HH + idx];
    __syncthreads();
    float Areg[4][8];
    #pragma unroll
    for (int i = 0; i < 4; i++) {
        size_t gb = ((size_t)b * SS + s0 + tr * 4 + i) * HH + tc * 8;
        *(float4*)&Areg[i][0] = *(const float4*)&Ag[gb];
        *(float4*)&Areg[i][4] = *(const float4*)&Ag[gb + 4];
    }
    float w2a[8];
    *(float4*)&w2a[0] = *(const float4*)&au_w2[tc * 8];
    *(float4*)&w2a[4] = *(const float4*)&au_w2[tc * 8 + 4];
    float bias2 = au_b2[0];
    for (int n = 0; n < NN; n++) {
        for (int idx = tid; idx < 64 * HH; idx += 256) {
            int r = idx >> 7, c = idx & 127;
            xs[r * 129 + c] = x2[((size_t)b * SS + s0 + r) * HH + c] * xns[n * HH + c];
        }
        __syncthreads();
        float acc[4][8] = {};
        #pragma unroll 2
        for (int hh = 0; hh < HH; hh++) {
            float a0 = xs[(tr * 4 + 0) * 129 + hh];
            float a1 = xs[(tr * 4 + 1) * 129 + hh];
            float a2 = xs[(tr * 4 + 2) * 129 + hh];
            float a3 = xs[(tr * 4 + 3) * 129 + hh];
            float4 w0 = *(float4*)&W2s[hh * HH + tc * 8];
            float4 w1 = *(float4*)&W2s[hh * HH + tc * 8 + 4];
            acc[0][0] += a0 * w0.x; acc[0][1] += a0 * w0.y; acc[0][2] += a0 * w0.z; acc[0][3] += a0 * w0.w;
            acc[0][4] += a0 * w1.x; acc[0][5] += a0 * w1.y; acc[0][6] += a0 * w1.z; acc[0][7] += a0 * w1.w;
            acc[1][0] += a1 * w0.x; acc[1][1] += a1 * w0.y; acc[1][2] += a1 * w0.z; acc[1][3] += a1 * w0.w;
            acc[1][4] += a1 * w1.x; acc[1][5] += a1 * w1.y; acc[1][6] += a1 * w1.z; acc[1][7] += a1 * w1.w;
            acc[2][0] += a2 * w0.x; acc[2][1] += a2 * w0.y; acc[2][2] += a2 * w0.z; acc[2][3] += a2 * w0.w;
            acc[2][4] += a2 * w1.x; acc[2][5] += a2 * w1.y; acc[2][6] += a2 * w1.z; acc[2][7] += a2 * w1.w;
            acc[3][0] += a3 * w0.x; acc[3][1] += a3 * w0.y; acc[3][2] += a3 * w0.z; acc[3][3] += a3 * w0.w;
            acc[3][4] += a3 * w1.x; acc[3][5] += a3 * w1.y; acc[3][6] += a3 * w1.z; acc[3][7] += a3 * w1.w;
        }
        float Bn[8];
        size_t bb = ((size_t)b * NN + n) * HH + tc * 8;
        *(float4*)&Bn[0] = *(const float4*)&Bng[bb];
        *(float4*)&Bn[4] = *(const float4*)&Bng[bb + 4];
        #pragma unroll
        for (int i = 0; i < 4; i++) {
            float p = 0.0f;
            #pragma unroll
            for (int j = 0; j < 8; j++) {
                float vv = acc[i][j] + Areg[i][j] + Bn[j];
                vv = fmaxf(vv, 0.0f);
                p += vv * w2a[j];
            }
            #pragma unroll
            for (int o = 8; o > 0; o >>= 1) p += __shfl_xor_sync(0xffffffffu, p, o);
            if (tc == 0) logits[(tr * 4 + i) * 17 + n] = p + bias2;
        }
        __syncthreads();
    }
    if (tid < 64) {
        float m = -1e30f;
        #pragma unroll
        for (int n = 0; n < NN; n++) m = fmaxf(m, logits[tid * 17 + n]);
        float l = 0.0f;
        #pragma unroll
        for (int n = 0; n < NN; n++) {
            float p = fast_exp(logits[tid * 17 + n] - m);
            logits[tid * 17 + n] = p; l += p;
        }
        float inv = 1.0f / l;
        #pragma unroll
        for (int n = 0; n < NN; n++) logits[tid * 17 + n] *= inv;
    }
    __syncthreads();
    for (int idx = tid; idx < 64 * HH; idx += 256) {
        int r = idx >> 7, c = idx & 127;
        float o = x2[((size_t)b * SS + s0 + r) * HH + c];
        #pragma unroll
        for (int n = 0; n < NN; n++) o += logits[r * 17 + n] * xns[n * HH + c];
        out[((size_t)b * SS + s0 + r) * HH + c] = o;
    }
}

// ---------------- launch ----------------
extern "C" void kernel_launch(void* const* d_in, const int* in_sizes, int n_in,
                              void* d_out, int out_size) {
    const float* x      = (const float*)d_in[0];
    const int*   mask   = (const int*)  d_in[1];
    const float* neighs = (const float*)d_in[2];
    const int*   nmask  = (const int*)  d_in[3];
    const float* wq = (const float*)d_in[4];  const float* bq = (const float*)d_in[5];
    const float* wk = (const float*)d_in[6];  const float* bk = (const float*)d_in[7];
    const float* wv = (const float*)d_in[8];  const float* bv = (const float*)d_in[9];
    const float* wo = (const float*)d_in[10]; const float* bo = (const float*)d_in[11];
    const float* ln1_g = (const float*)d_in[12]; const float* ln1_b = (const float*)d_in[13];
    const float* ln2_g = (const float*)d_in[14]; const float* ln2_b = (const float*)d_in[15];
    const float* ff_w1 = (const float*)d_in[16]; const float* ff_b1 = (const float*)d_in[17];
    const float* ff_w2 = (const float*)d_in[18]; const float* ff_b2 = (const float*)d_in[19];
    const float* au_w1 = (const float*)d_in[20]; const float* au_b1 = (const float*)d_in[21];
    const float* au_w2 = (const float*)d_in[22]; const float* au_b2 = (const float*)d_in[23];
    float* out = (float*)d_out;

    float *p_xn, *p_qkv, *p_attn, *p_x1, *p_h, *p_ffh, *p_x2, *p_A,
          *p_xnei, *p_Bn, *p_Wd, *p_Wnc, *p_Wqkv, *p_bqkv;
    cudaGetSymbolAddress((void**)&p_xn, g_xn);
    cudaGetSymbolAddress((void**)&p_qkv, g_qkv);
    cudaGetSymbolAddress((void**)&p_attn, g_attn);
    cudaGetSymbolAddress((void**)&p_x1, g_x1);
    cudaGetSymbolAddress((void**)&p_h, g_h);
    cudaGetSymbolAddress((void**)&p_ffh, g_ffh);
    cudaGetSymbolAddress((void**)&p_x2, g_x2);
    cudaGetSymbolAddress((void**)&p_A, g_A);
    cudaGetSymbolAddress((void**)&p_xnei, g_xnei);
    cudaGetSymbolAddress((void**)&p_Bn, g_Bn);
    cudaGetSymbolAddress((void**)&p_Wd, g_Wd);
    cudaGetSymbolAddress((void**)&p_Wnc, g_Wnc);
    cudaGetSymbolAddress((void**)&p_Wqkv, g_Wqkv);
    cudaGetSymbolAddress((void**)&p_bqkv, g_bqkv);

    const int neigh_shmem = (64 * 129 * 2 + 128 + 128 + 256) * 4;            // ~68 KB
    const int au_shmem = (16384 + 64 * 129 + 2048 + 64 * 17) * 4;            // ~111 KB
    cudaFuncSetAttribute(neigh_kernel, cudaFuncAttributeMaxDynamicSharedMemorySize, neigh_shmem);
    cudaFuncSetAttribute(au_kernel, cudaFuncAttributeMaxDynamicSharedMemorySize, au_shmem);

    prep_kernel<<<192, 256>>>(au_w1, wq, wk, wv, bq, bk, bv, p_Wd, p_Wnc, p_Wqkv, p_bqkv);
    ln_kernel<<<ROWS, 128>>>(x, ln1_g, ln1_b, p_xn);
    {
        dim3 g(384 / TBN, ROWS / TBM);
        sgemm128<<<g, 256>>>(p_xn, p_Wqkv, p_bqkv, nullptr, p_qkv, ROWS, HH, 384, 0);
    }
    attn_kernel<<<BB * NHEADS * 8, 256>>>(p_qkv, mask, p_attn);
    {
        dim3 g(1, ROWS / TBM);
        sgemm128<<<g, 256>>>(p_attn, wo, bo, x, p_x1, ROWS, HH, HH, 0);
    }
    neigh_kernel<<<NN * BB, 256, neigh_shmem>>>(neighs, nmask, wq, bq, wk, bk, wv, bv,
                                                wo, bo, ln1_g, ln1_b, p_xnei);
    ln_kernel<<<ROWS, 128>>>(p_x1, ln2_g, ln2_b, p_h);
    {
        dim3 g(FFD / TBN, ROWS / TBM);
        sgemm128<<<g, 256>>>(p_h, ff_w1, ff_b1, nullptr, p_ffh, ROWS, HH, FFD, 1);
    }
    {
        dim3 g(1, ROWS / TBM);
        sgemm128<<<g, 256>>>(p_ffh, ff_w2, ff_b2, p_x1, p_x2, ROWS, FFD, HH, 0);
    }
    {
        dim3 g(1, ROWS / TBM);
        sgemm128<<<g, 256>>>(p_x2, p_Wd, au_b1, nullptr, p_A, ROWS, HH, HH, 0);
    }
    {
        dim3 g(1, (BB * NN) / TBM);
        sgemm128<<<g, 256>>>(p_xnei, p_Wnc, nullptr, nullptr, p_Bn, BB * NN, HH, HH, 0);
    }
    {
        dim3 g(SS / 64, BB);
        au_kernel<<<g, 256, au_shmem>>>(p_x2, p_A, p_Bn, p_xnei, au_w1, au_w2, au_b2, out);
    }
}

// round 4
// speedup vs baseline: 2.1608x; 1.8799x over previous
#include <cuda_runtime.h>
#include <cuda_bf16.h>
#include <math.h>

// Problem dims
#define BB 32
#define SS 512
#define HH 128
#define NHEADS 4
#define DD 32
#define FFD 512
#define NN 16
#define SNN 64
#define ROWS (BB*SS)          // 16384

// ---------------- static device scratch ----------------
__device__ float g_xn  [ROWS*HH];
__device__ float g_qkv [ROWS*384];
__device__ float g_attn[ROWS*HH];
__device__ float g_x1  [ROWS*HH];
__device__ float g_h   [ROWS*HH];
__device__ float g_ffh [ROWS*FFD];
__device__ float g_x2  [ROWS*HH];
__device__ float g_A   [ROWS*HH];
__device__ float g_xnei[BB*NN*HH];
__device__ float g_Bn  [BB*NN*HH];
__device__ float g_Wd  [HH*HH];
__device__ float g_Wnc [HH*HH];
__device__ float g_Wqkv[HH*384];
__device__ float g_bqkv[384];

// ---------------- tf32 / mma helpers --------------------------------------
__device__ __forceinline__ unsigned f2tf(float f) {
    unsigned r;
    asm("cvt.rna.tf32.f32 %0, %1;" : "=r"(r) : "f"(f));
    return r;
}
__device__ __forceinline__ float f2tf_f(float f) { return __uint_as_float(f2tf(f)); }

__device__ __forceinline__ void mma_tf32(float* c, const unsigned* a, const unsigned* b) {
    asm volatile(
        "mma.sync.aligned.m16n8k8.row.col.f32.tf32.tf32.f32 "
        "{%0,%1,%2,%3}, {%4,%5,%6,%7}, {%8,%9}, {%0,%1,%2,%3};"
        : "+f"(c[0]), "+f"(c[1]), "+f"(c[2]), "+f"(c[3])
        : "r"(a[0]), "r"(a[1]), "r"(a[2]), "r"(a[3]), "r"(b[0]), "r"(b[1]));
}

// ---------------- fast exp: FMA-pipe polynomial (no MUFU) ----------------
__device__ __forceinline__ float fast_exp(float x) {
    float z = x * 1.4426950408889634f;
    z = fminf(fmaxf(z, -126.0f), 126.0f);
    float t = z + 12582912.0f;
    int n = __float_as_int(t) - 0x4B400000;
    float f = z - (t - 12582912.0f);
    float p = 0.0013333558f;
    p = fmaf(p, f, 0.0096181291f);
    p = fmaf(p, f, 0.0555041087f);
    p = fmaf(p, f, 0.2402265070f);
    p = fmaf(p, f, 0.6931471806f);
    p = fmaf(p, f, 1.0f);
    return __int_as_float(__float_as_int(p) + (n << 23));
}

__device__ __forceinline__ float gelu_fast(float x) {
    float u = 0.7978845608028654f * (x + 0.044715f * x * x * x);
    float t = fast_exp(-2.0f * u);
    return __fdividef(x, 1.0f + t);
}

// ---------------- prep ------------------------------------------------------
__global__ void prep_kernel(const float* __restrict__ au_w1,
                            const float* __restrict__ wq, const float* __restrict__ wk,
                            const float* __restrict__ wv,
                            const float* __restrict__ bq, const float* __restrict__ bk,
                            const float* __restrict__ bv,
                            float* __restrict__ Wd, float* __restrict__ Wnc,
                            float* __restrict__ Wqkv, float* __restrict__ bqkv) {
    int idx = blockIdx.x * blockDim.x + threadIdx.x;
    if (idx < HH * HH) {
        int h = idx >> 7, j = idx & 127;
        float w1 = au_w1[h * HH + j];
        float w3 = au_w1[(256 + h) * HH + j];
        float w4 = au_w1[(384 + h) * HH + j];
        Wd[idx]  = w1 - w3;
        Wnc[idx] = w3 + w4;
    }
    if (idx < HH * 384) {
        int h = idx / 384, c = idx % 384;
        float v = (c < 128) ? wq[h * 128 + c]
                 : (c < 256) ? wk[h * 128 + (c - 128)]
                             : wv[h * 128 + (c - 256)];
        Wqkv[idx] = v;
    }
    if (idx < 384) {
        bqkv[idx] = (idx < 128) ? bq[idx] : (idx < 256) ? bk[idx - 128] : bv[idx - 256];
    }
}

// ---------------- layernorm ------------------------------------------------
__global__ void ln_kernel(const float* __restrict__ x, const float* __restrict__ g,
                          const float* __restrict__ b, float* __restrict__ y) {
    int row = blockIdx.x;
    int t = threadIdx.x;
    float v = x[(size_t)row * HH + t];
    float s = v, s2 = v * v;
    #pragma unroll
    for (int o = 16; o > 0; o >>= 1) {
        s  += __shfl_xor_sync(0xffffffffu, s, o);
        s2 += __shfl_xor_sync(0xffffffffu, s2, o);
    }
    __shared__ float ws[8];
    if ((t & 31) == 0) { ws[t >> 5] = s; ws[4 + (t >> 5)] = s2; }
    __syncthreads();
    s  = ws[0] + ws[1] + ws[2] + ws[3];
    s2 = ws[4] + ws[5] + ws[6] + ws[7];
    float mean = s * (1.0f / HH);
    float var = s2 * (1.0f / HH) - mean * mean;
    float rs = rsqrtf(var + 1e-6f);
    y[(size_t)row * HH + t] = (v - mean) * rs * g[t] + b[t];
}

// ---------------- TF32 tensor-core GEMM: 128x128 tile, 8 warps -------------
#define TBM 128
#define TBN 128
#define TBK 16
__global__ __launch_bounds__(256) void sgemm_tc(
    const float* __restrict__ A, const float* __restrict__ W,
    const float* __restrict__ bias, const float* __restrict__ res,
    float* __restrict__ C, int M, int K, int N, int act) {
    __shared__ float As[2][TBK][132];
    __shared__ float Ws[2][TBK][132];
    int bm = blockIdx.y * TBM, bn = blockIdx.x * TBN;
    int tid = threadIdx.x;
    int wid = tid >> 5, lane = tid & 31;
    int gid = lane >> 2, tig = lane & 3;
    int wm = (wid >> 2) * 64, wn = (wid & 3) * 32;
    int arow[2], ac4[2], wrow[2], wc4[2];
    #pragma unroll
    for (int l = 0; l < 2; l++) {
        int L = l * 256 + tid;
        arow[l] = L >> 2;  ac4[l] = L & 3;
        wrow[l] = L >> 5;  wc4[l] = L & 31;
    }
    float4 aL[2], wL[2];
    #pragma unroll
    for (int l = 0; l < 2; l++) {
        aL[l] = *(const float4*)&A[(size_t)(bm + arow[l]) * K + ac4[l] * 4];
        wL[l] = *(const float4*)&W[(size_t)wrow[l] * N + bn + wc4[l] * 4];
    }
    #pragma unroll
    for (int l = 0; l < 2; l++) {
        As[0][ac4[l] * 4 + 0][arow[l]] = f2tf_f(aL[l].x);
        As[0][ac4[l] * 4 + 1][arow[l]] = f2tf_f(aL[l].y);
        As[0][ac4[l] * 4 + 2][arow[l]] = f2tf_f(aL[l].z);
        As[0][ac4[l] * 4 + 3][arow[l]] = f2tf_f(aL[l].w);
        Ws[0][wrow[l]][wc4[l] * 4 + 0] = f2tf_f(wL[l].x);
        Ws[0][wrow[l]][wc4[l] * 4 + 1] = f2tf_f(wL[l].y);
        Ws[0][wrow[l]][wc4[l] * 4 + 2] = f2tf_f(wL[l].z);
        Ws[0][wrow[l]][wc4[l] * 4 + 3] = f2tf_f(wL[l].w);
    }
    __syncthreads();
    float c[4][4][4] = {};
    int nk = K / TBK;
    for (int kt = 0; kt < nk; kt++) {
        int cur = kt & 1;
        if (kt + 1 < nk) {
            int k0 = (kt + 1) * TBK;
            #pragma unroll
            for (int l = 0; l < 2; l++) {
                aL[l] = *(const float4*)&A[(size_t)(bm + arow[l]) * K + k0 + ac4[l] * 4];
                wL[l] = *(const float4*)&W[(size_t)(k0 + wrow[l]) * N + bn + wc4[l] * 4];
            }
        }
        #pragma unroll
        for (int ks = 0; ks < 2; ks++) {
            int k0 = ks * 8;
            unsigned a[4][4], b[4][2];
            #pragma unroll
            for (int mt = 0; mt < 4; mt++) {
                a[mt][0] = __float_as_uint(As[cur][k0 + tig    ][wm + mt * 16 + gid]);
                a[mt][1] = __float_as_uint(As[cur][k0 + tig    ][wm + mt * 16 + gid + 8]);
                a[mt][2] = __float_as_uint(As[cur][k0 + tig + 4][wm + mt * 16 + gid]);
                a[mt][3] = __float_as_uint(As[cur][k0 + tig + 4][wm + mt * 16 + gid + 8]);
            }
            #pragma unroll
            for (int nt = 0; nt < 4; nt++) {
                b[nt][0] = __float_as_uint(Ws[cur][k0 + tig    ][wn + nt * 8 + gid]);
                b[nt][1] = __float_as_uint(Ws[cur][k0 + tig + 4][wn + nt * 8 + gid]);
            }
            #pragma unroll
            for (int mt = 0; mt < 4; mt++)
                #pragma unroll
                for (int nt = 0; nt < 4; nt++)
                    mma_tf32(c[mt][nt], a[mt], b[nt]);
        }
        if (kt + 1 < nk) {
            int nxt = cur ^ 1;
            #pragma unroll
            for (int l = 0; l < 2; l++) {
                As[nxt][ac4[l] * 4 + 0][arow[l]] = f2tf_f(aL[l].x);
                As[nxt][ac4[l] * 4 + 1][arow[l]] = f2tf_f(aL[l].y);
                As[nxt][ac4[l] * 4 + 2][arow[l]] = f2tf_f(aL[l].z);
                As[nxt][ac4[l] * 4 + 3][arow[l]] = f2tf_f(aL[l].w);
                Ws[nxt][wrow[l]][wc4[l] * 4 + 0] = f2tf_f(wL[l].x);
                Ws[nxt][wrow[l]][wc4[l] * 4 + 1] = f2tf_f(wL[l].y);
                Ws[nxt][wrow[l]][wc4[l] * 4 + 2] = f2tf_f(wL[l].z);
                Ws[nxt][wrow[l]][wc4[l] * 4 + 3] = f2tf_f(wL[l].w);
            }
        }
        __syncthreads();
    }
    // epilogue
    #pragma unroll
    for (int mt = 0; mt < 4; mt++) {
        #pragma unroll
        for (int nt = 0; nt < 4; nt++) {
            int col = bn + wn + nt * 8 + tig * 2;
            float b0 = bias ? bias[col] : 0.0f;
            float b1 = bias ? bias[col + 1] : 0.0f;
            #pragma unroll
            for (int hh = 0; hh < 2; hh++) {
                int row = bm + wm + mt * 16 + gid + hh * 8;
                float v0 = c[mt][nt][hh * 2 + 0] + b0;
                float v1 = c[mt][nt][hh * 2 + 1] + b1;
                if (act == 1) { v0 = gelu_fast(v0); v1 = gelu_fast(v1); }
                if (res) {
                    const float2 rv = *(const float2*)&res[(size_t)row * N + col];
                    v0 += rv.x; v1 += rv.y;
                }
                float2 ov; ov.x = v0; ov.y = v1;
                *(float2*)&C[(size_t)row * N + col] = ov;
            }
        }
    }
}

// ---------------- flash attention with tf32 mma ----------------------------
// block = (b, h, q-tile 64); 128 threads (4 warps), warp w owns q rows w*16..+15
__global__ __launch_bounds__(128) void attn_kernel(const float* __restrict__ qkv,
                                                   const int* __restrict__ mask,
                                                   float* __restrict__ o) {
    __shared__ float Qs[64][36];
    __shared__ float Ks[64][36];
    __shared__ float Vs[64][36];
    __shared__ float Ps[64][68];
    int blk = blockIdx.x;
    int qt = blk & 7, h = (blk >> 3) & 3, b = blk >> 5;
    int q0 = qt * 64;
    int tid = threadIdx.x;
    int w = tid >> 5, lane = tid & 31;
    int gid = lane >> 2, tig = lane & 3;
    const float* qbase = qkv + (size_t)(b * SS + q0) * 384 + h * 32;
    const float scale = 0.17677669529663687f;
    #pragma unroll
    for (int k = 0; k < 4; k++) {
        int idx = tid + k * 128;
        int r = idx >> 3, c4 = idx & 7;
        float4 v = *(const float4*)&qbase[(size_t)r * 384 + c4 * 4];
        Qs[r][c4 * 4 + 0] = f2tf_f(v.x * scale);
        Qs[r][c4 * 4 + 1] = f2tf_f(v.y * scale);
        Qs[r][c4 * 4 + 2] = f2tf_f(v.z * scale);
        Qs[r][c4 * 4 + 3] = f2tf_f(v.w * scale);
    }
    float o_acc[4][4] = {};
    float m0 = -1e30f, l0 = 0.0f, m1 = -1e30f, l1 = 0.0f;
    const int* mbase = mask + (size_t)b * SS * SS + (size_t)q0 * SS;
    const float* kbase = qkv + (size_t)b * SS * 384 + 128 + h * 32;
    const float* vbase = qkv + (size_t)b * SS * 384 + 256 + h * 32;
    for (int kt = 0; kt < 8; kt++) {
        int c0k = kt * 64;
        __syncthreads();
        #pragma unroll
        for (int k = 0; k < 4; k++) {
            int idx = tid + k * 128;
            int r = idx >> 3, c4 = idx & 7;
            float4 kv4 = *(const float4*)&kbase[(size_t)(c0k + r) * 384 + c4 * 4];
            float4 vv4 = *(const float4*)&vbase[(size_t)(c0k + r) * 384 + c4 * 4];
            Ks[r][c4 * 4 + 0] = f2tf_f(kv4.x);
            Ks[r][c4 * 4 + 1] = f2tf_f(kv4.y);
            Ks[r][c4 * 4 + 2] = f2tf_f(kv4.z);
            Ks[r][c4 * 4 + 3] = f2tf_f(kv4.w);
            Vs[r][c4 * 4 + 0] = f2tf_f(vv4.x);
            Vs[r][c4 * 4 + 1] = f2tf_f(vv4.y);
            Vs[r][c4 * 4 + 2] = f2tf_f(vv4.z);
            Vs[r][c4 * 4 + 3] = f2tf_f(vv4.w);
        }
        __syncthreads();
        // S = Q @ K^T : per-warp 16x64
        float cs[8][4] = {};
        #pragma unroll
        for (int ks = 0; ks < 4; ks++) {
            int k0 = ks * 8;
            unsigned a[4];
            a[0] = __float_as_uint(Qs[w * 16 + gid    ][k0 + tig]);
            a[1] = __float_as_uint(Qs[w * 16 + gid + 8][k0 + tig]);
            a[2] = __float_as_uint(Qs[w * 16 + gid    ][k0 + tig + 4]);
            a[3] = __float_as_uint(Qs[w * 16 + gid + 8][k0 + tig + 4]);
            #pragma unroll
            for (int nt = 0; nt < 8; nt++) {
                unsigned bb[2];
                bb[0] = __float_as_uint(Ks[nt * 8 + gid][k0 + tig]);
                bb[1] = __float_as_uint(Ks[nt * 8 + gid][k0 + tig + 4]);
                mma_tf32(cs[nt], a, bb);
            }
        }
        // mask + online softmax (rows r0 = w*16+gid, r1 = +8)
        const int* mr0 = mbase + (size_t)(w * 16 + gid) * SS + c0k;
        const int* mr1 = mr0 + 8 * SS;
        float sv0[16], sv1[16];
        #pragma unroll
        for (int nt = 0; nt < 8; nt++) {
            #pragma unroll
            for (int cc = 0; cc < 2; cc++) {
                int ncol = nt * 8 + tig * 2 + cc;
                float s0 = cs[nt][cc];
                float s1 = cs[nt][2 + cc];
                if (mr0[ncol] == 0) s0 = -1e9f;
                if (mr1[ncol] == 0) s1 = -1e9f;
                sv0[nt * 2 + cc] = s0;
                sv1[nt * 2 + cc] = s1;
            }
        }
        float t0 = sv0[0], t1 = sv1[0];
        #pragma unroll
        for (int i = 1; i < 16; i++) { t0 = fmaxf(t0, sv0[i]); t1 = fmaxf(t1, sv1[i]); }
        t0 = fmaxf(t0, __shfl_xor_sync(0xffffffffu, t0, 1));
        t0 = fmaxf(t0, __shfl_xor_sync(0xffffffffu, t0, 2));
        t1 = fmaxf(t1, __shfl_xor_sync(0xffffffffu, t1, 1));
        t1 = fmaxf(t1, __shfl_xor_sync(0xffffffffu, t1, 2));
        float mn0 = fmaxf(m0, t0), mn1 = fmaxf(m1, t1);
        float corr0 = fast_exp(m0 - mn0), corr1 = fast_exp(m1 - mn1);
        float ps0 = 0.0f, ps1 = 0.0f;
        #pragma unroll
        for (int i = 0; i < 16; i++) {
            float p0 = fast_exp(sv0[i] - mn0);
            float p1 = fast_exp(sv1[i] - mn1);
            sv0[i] = p0; sv1[i] = p1;
            ps0 += p0; ps1 += p1;
        }
        ps0 += __shfl_xor_sync(0xffffffffu, ps0, 1);
        ps0 += __shfl_xor_sync(0xffffffffu, ps0, 2);
        ps1 += __shfl_xor_sync(0xffffffffu, ps1, 1);
        ps1 += __shfl_xor_sync(0xffffffffu, ps1, 2);
        l0 = l0 * corr0 + ps0; m0 = mn0;
        l1 = l1 * corr1 + ps1; m1 = mn1;
        #pragma unroll
        for (int nt = 0; nt < 4; nt++) {
            o_acc[nt][0] *= corr0; o_acc[nt][1] *= corr0;
            o_acc[nt][2] *= corr1; o_acc[nt][3] *= corr1;
        }
        // write P (tf32) to shared
        #pragma unroll
        for (int nt = 0; nt < 8; nt++) {
            #pragma unroll
            for (int cc = 0; cc < 2; cc++) {
                int ncol = nt * 8 + tig * 2 + cc;
                Ps[w * 16 + gid    ][ncol] = f2tf_f(sv0[nt * 2 + cc]);
                Ps[w * 16 + gid + 8][ncol] = f2tf_f(sv1[nt * 2 + cc]);
            }
        }
        __syncwarp();
        // O += P @ V : 16x32, k=64
        #pragma unroll
        for (int ks = 0; ks < 8; ks++) {
            int k0 = ks * 8;
            unsigned a[4];
            a[0] = __float_as_uint(Ps[w * 16 + gid    ][k0 + tig]);
            a[1] = __float_as_uint(Ps[w * 16 + gid + 8][k0 + tig]);
            a[2] = __float_as_uint(Ps[w * 16 + gid    ][k0 + tig + 4]);
            a[3] = __float_as_uint(Ps[w * 16 + gid + 8][k0 + tig + 4]);
            #pragma unroll
            for (int nt = 0; nt < 4; nt++) {
                unsigned bb[2];
                bb[0] = __float_as_uint(Vs[k0 + tig    ][nt * 8 + gid]);
                bb[1] = __float_as_uint(Vs[k0 + tig + 4][nt * 8 + gid]);
                mma_tf32(o_acc[nt], a, bb);
            }
        }
    }
    // epilogue
    float inv0 = __fdividef(1.0f, l0);
    float inv1 = __fdividef(1.0f, l1);
    #pragma unroll
    for (int nt = 0; nt < 4; nt++) {
        int col = h * 32 + nt * 8 + tig * 2;
        size_t row0 = (size_t)(b * SS + q0 + w * 16 + gid);
        float2 v0; v0.x = o_acc[nt][0] * inv0; v0.y = o_acc[nt][1] * inv0;
        *(float2*)&o[row0 * HH + col] = v0;
        float2 v1; v1.x = o_acc[nt][2] * inv1; v1.y = o_acc[nt][3] * inv1;
        *(float2*)&o[(row0 + 8) * HH + col] = v1;
    }
}

// ---------------- neighbor proj helper -------------------------------------
__device__ __forceinline__ void proj64(const float* ln, const float* __restrict__ W,
                                       const float* __restrict__ bias, float* out, int tid) {
    int c2 = (tid & 63) * 2;
    int q4 = tid >> 6;
    int r0 = q4 * 16;
    float acc0[16], acc1[16];
    float bv0 = bias[c2], bv1 = bias[c2 + 1];
    #pragma unroll
    for (int i = 0; i < 16; i++) { acc0[i] = bv0; acc1[i] = bv1; }
    #pragma unroll 4
    for (int hh = 0; hh < HH; hh++) {
        float2 w = *(const float2*)&W[hh * HH + c2];
        #pragma unroll
        for (int i = 0; i < 16; i++) {
            float a = ln[(r0 + i) * 129 + hh];
            acc0[i] += a * w.x;
            acc1[i] += a * w.y;
        }
    }
    #pragma unroll
    for (int i = 0; i < 16; i++) {
        out[(r0 + i) * 129 + c2] = acc0[i];
        out[(r0 + i) * 129 + c2 + 1] = acc1[i];
    }
}

// ---------------- neighbor attention (last-token only) ---------------------
__global__ void neigh_kernel(const float* __restrict__ neighs, const int* __restrict__ nmask,
                             const float* __restrict__ wq, const float* __restrict__ bq,
                             const float* __restrict__ wk, const float* __restrict__ bk,
                             const float* __restrict__ wv, const float* __restrict__ bv,
                             const float* __restrict__ wo, const float* __restrict__ bo,
                             const float* __restrict__ g1, const float* __restrict__ b1,
                             float* __restrict__ xnei) {
    extern __shared__ float sh[];
    float* ln  = sh;
    float* kv  = ln + 64 * 129;
    float* qv  = kv + 64 * 129;
    float* osh = qv + 128;
    float* sc  = osh + 128;
    int tid = threadIdx.x;
    int nb = blockIdx.x;
    int n = nb / BB, b = nb % BB;
    const float* base = neighs + (size_t)nb * SNN * HH;
    for (int idx = tid; idx < SNN * HH; idx += 256) {
        int r = idx >> 7, c = idx & 127;
        ln[r * 129 + c] = base[idx];
    }
    __syncthreads();
    {
        int warp = tid >> 5, lane = tid & 31;
        for (int r = warp; r < SNN; r += 8) {
            float s = 0.0f, s2 = 0.0f;
            #pragma unroll
            for (int c = lane; c < HH; c += 32) {
                float v = ln[r * 129 + c];
                s += v; s2 += v * v;
            }
            #pragma unroll
            for (int o = 16; o > 0; o >>= 1) {
                s  += __shfl_xor_sync(0xffffffffu, s, o);
                s2 += __shfl_xor_sync(0xffffffffu, s2, o);
            }
            float mean = s * (1.0f / HH);
            float var = s2 * (1.0f / HH) - mean * mean;
            float rs = rsqrtf(var + 1e-6f);
            #pragma unroll
            for (int c = lane; c < HH; c += 32) {
                float v = ln[r * 129 + c];
                ln[r * 129 + c] = (v - mean) * rs * g1[c] + b1[c];
            }
        }
    }
    __syncthreads();
    proj64(ln, wk, bk, kv, tid);
    if (tid < HH) {
        float a = bq[tid];
        #pragma unroll 4
        for (int hh = 0; hh < HH; hh++) a += ln[63 * 129 + hh] * wq[hh * HH + tid];
        qv[tid] = a;
    }
    __syncthreads();
    {
        int head = tid >> 6, j = tid & 63;
        float s = 0.0f;
        #pragma unroll
        for (int d = 0; d < DD; d++) s += qv[head * DD + d] * kv[j * 129 + head * DD + d];
        s *= 0.17677669529663687f;
        int mval = nmask[((size_t)nb * SNN + (SNN - 1)) * SNN + j];
        if (mval == 0) s = -1e9f;
        sc[head * 64 + j] = s;
    }
    __syncthreads();
    if (tid < 4) {
        float m = -1e30f;
        for (int j = 0; j < 64; j++) m = fmaxf(m, sc[tid * 64 + j]);
        float l = 0.0f;
        for (int j = 0; j < 64; j++) {
            float p = fast_exp(sc[tid * 64 + j] - m);
            sc[tid * 64 + j] = p; l += p;
        }
        float inv = 1.0f / l;
        for (int j = 0; j < 64; j++) sc[tid * 64 + j] *= inv;
    }
    __syncthreads();
    proj64(ln, wv, bv, kv, tid);
    __syncthreads();
    if (tid < HH) {
        int head = tid >> 5;
        float o = 0.0f;
        #pragma unroll 4
        for (int j = 0; j < 64; j++) o += sc[head * 64 + j] * kv[j * 129 + tid];
        osh[tid] = o;
    }
    __syncthreads();
    if (tid < HH) {
        float r = bo[tid] + base[(SNN - 1) * HH + tid];
        #pragma unroll 4
        for (int hh = 0; hh < HH; hh++) r += osh[hh] * wo[hh * HH + tid];
        xnei[((size_t)b * NN + n) * HH + tid] = r;
    }
}

// ---------------- attention-pooling kernel (tf32 mma) ----------------------
// block = (b, 64 s-rows), 256 threads (8 warps). warp w owns W2-cols w*16..+15.
__global__ __launch_bounds__(256) void au_kernel(
        const float* __restrict__ x2, const float* __restrict__ Ag,
        const float* __restrict__ Bng, const float* __restrict__ xnei,
        const float* __restrict__ au_w1, const float* __restrict__ au_w2,
        const float* __restrict__ au_b2, float* __restrict__ out) {
    extern __shared__ float sh[];
    float* x2s    = sh;                  // 64*132 fp32
    float* W2s    = x2s + 64 * 132;      // 128*132 tf32
    float* xns    = W2s + 128 * 132;     // 16*128 fp32
    float* logits = xns + 2048;          // 64*16
    int tid = threadIdx.x;
    int b = blockIdx.y;
    int s0 = blockIdx.x * 64;
    int w = tid >> 5, lane = tid & 31;
    int gid = lane >> 2, tig = lane & 3;
    int wn = w * 16;
    for (int idx = tid; idx < HH * HH; idx += 256) {
        int k = idx >> 7, nn = idx & 127;
        W2s[k * 132 + nn] = f2tf_f(au_w1[HH * HH + idx]);
    }
    for (int idx = tid; idx < 64 * HH; idx += 256) {
        int r = idx >> 7, cc = idx & 127;
        x2s[r * 132 + cc] = x2[((size_t)b * SS + s0 + r) * HH + cc];
    }
    for (int idx = tid; idx < NN * HH; idx += 256) xns[idx] = xnei[(size_t)b * NN * HH + idx];
    for (int idx = tid; idx < 64 * 16; idx += 256) logits[idx] = 0.0f;
    // per-thread fixed columns
    int colv[4];
    float w2r[4];
    #pragma unroll
    for (int q = 0; q < 4; q++) {
        colv[q] = wn + (q >> 1) * 8 + tig * 2 + (q & 1);
        w2r[q] = au_w2[colv[q]];
    }
    float Areg[8][4];
    #pragma unroll
    for (int mt = 0; mt < 4; mt++)
        #pragma unroll
        for (int hh = 0; hh < 2; hh++) {
            int r = mt * 16 + gid + hh * 8;
            #pragma unroll
            for (int q = 0; q < 4; q++)
                Areg[mt * 2 + hh][q] = Ag[((size_t)b * SS + s0 + r) * HH + colv[q]];
        }
    __syncthreads();
    for (int n = 0; n < NN; n++) {
        const float* xnp = xns + n * 128;
        float c[4][2][4] = {};
        #pragma unroll
        for (int ks = 0; ks < 16; ks++) {
            int k0 = ks * 8;
            float xn0 = xnp[k0 + tig];
            float xn4 = xnp[k0 + tig + 4];
            unsigned bfr[2][2];
            #pragma unroll
            for (int nt = 0; nt < 2; nt++) {
                bfr[nt][0] = __float_as_uint(W2s[(k0 + tig) * 132 + wn + nt * 8 + gid]);
                bfr[nt][1] = __float_as_uint(W2s[(k0 + tig + 4) * 132 + wn + nt * 8 + gid]);
            }
            #pragma unroll
            for (int mt = 0; mt < 4; mt++) {
                unsigned a[4];
                a[0] = f2tf(x2s[(mt * 16 + gid) * 132 + k0 + tig] * xn0);
                a[1] = f2tf(x2s[(mt * 16 + gid + 8) * 132 + k0 + tig] * xn0);
                a[2] = f2tf(x2s[(mt * 16 + gid) * 132 + k0 + tig + 4] * xn4);
                a[3] = f2tf(x2s[(mt * 16 + gid + 8) * 132 + k0 + tig + 4] * xn4);
                mma_tf32(c[mt][0], a, bfr[0]);
                mma_tf32(c[mt][1], a, bfr[1]);
            }
        }
        float BnR[4];
        #pragma unroll
        for (int q = 0; q < 4; q++)
            BnR[q] = Bng[((size_t)b * NN + n) * HH + colv[q]];
        #pragma unroll
        for (int mt = 0; mt < 4; mt++) {
            float part0 = 0.0f, part1 = 0.0f;
            #pragma unroll
            for (int nt = 0; nt < 2; nt++)
                #pragma unroll
                for (int cc = 0; cc < 2; cc++) {
                    int q = nt * 2 + cc;
                    float v0 = c[mt][nt][cc]     + Areg[mt * 2][q]     + BnR[q];
                    float v1 = c[mt][nt][2 + cc] + Areg[mt * 2 + 1][q] + BnR[q];
                    part0 += fmaxf(v0, 0.0f) * w2r[q];
                    part1 += fmaxf(v1, 0.0f) * w2r[q];
                }
            part0 += __shfl_xor_sync(0xffffffffu, part0, 1);
            part0 += __shfl_xor_sync(0xffffffffu, part0, 2);
            part1 += __shfl_xor_sync(0xffffffffu, part1, 1);
            part1 += __shfl_xor_sync(0xffffffffu, part1, 2);
            if (tig == 0) {
                atomicAdd(&logits[(mt * 16 + gid) * 16 + n], part0);
                atomicAdd(&logits[(mt * 16 + gid + 8) * 16 + n], part1);
            }
        }
    }
    __syncthreads();
    if (tid < 64) {
        float m = -1e30f;
        #pragma unroll
        for (int n = 0; n < NN; n++) m = fmaxf(m, logits[tid * 16 + n]);
        float l = 0.0f;
        #pragma unroll
        for (int n = 0; n < NN; n++) {
            float p = fast_exp(logits[tid * 16 + n] - m);
            logits[tid * 16 + n] = p; l += p;
        }
        float inv = __fdividef(1.0f, l);
        #pragma unroll
        for (int n = 0; n < NN; n++) logits[tid * 16 + n] *= inv;
    }
    __syncthreads();
    for (int idx = tid; idx < 64 * HH; idx += 256) {
        int r = idx >> 7, cc = idx & 127;
        float o = x2s[r * 132 + cc];
        #pragma unroll
        for (int n = 0; n < NN; n++) o += logits[r * 16 + n] * xns[n * HH + cc];
        out[((size_t)b * SS + s0 + r) * HH + cc] = o;
    }
}

// ---------------- launch ----------------
extern "C" void kernel_launch(void* const* d_in, const int* in_sizes, int n_in,
                              void* d_out, int out_size) {
    const float* x      = (const float*)d_in[0];
    const int*   mask   = (const int*)  d_in[1];
    const float* neighs = (const float*)d_in[2];
    const int*   nmask  = (const int*)  d_in[3];
    const float* wq = (const float*)d_in[4];  const float* bq = (const float*)d_in[5];
    const float* wk = (const float*)d_in[6];  const float* bk = (const float*)d_in[7];
    const float* wv = (const float*)d_in[8];  const float* bv = (const float*)d_in[9];
    const float* wo = (const float*)d_in[10]; const float* bo = (const float*)d_in[11];
    const float* ln1_g = (const float*)d_in[12]; const float* ln1_b = (const float*)d_in[13];
    const float* ln2_g = (const float*)d_in[14]; const float* ln2_b = (const float*)d_in[15];
    const float* ff_w1 = (const float*)d_in[16]; const float* ff_b1 = (const float*)d_in[17];
    const float* ff_w2 = (const float*)d_in[18]; const float* ff_b2 = (const float*)d_in[19];
    const float* au_w1 = (const float*)d_in[20]; const float* au_b1 = (const float*)d_in[21];
    const float* au_w2 = (const float*)d_in[22]; const float* au_b2 = (const float*)d_in[23];
    float* out = (float*)d_out;

    float *p_xn, *p_qkv, *p_attn, *p_x1, *p_h, *p_ffh, *p_x2, *p_A,
          *p_xnei, *p_Bn, *p_Wd, *p_Wnc, *p_Wqkv, *p_bqkv;
    cudaGetSymbolAddress((void**)&p_xn, g_xn);
    cudaGetSymbolAddress((void**)&p_qkv, g_qkv);
    cudaGetSymbolAddress((void**)&p_attn, g_attn);
    cudaGetSymbolAddress((void**)&p_x1, g_x1);
    cudaGetSymbolAddress((void**)&p_h, g_h);
    cudaGetSymbolAddress((void**)&p_ffh, g_ffh);
    cudaGetSymbolAddress((void**)&p_x2, g_x2);
    cudaGetSymbolAddress((void**)&p_A, g_A);
    cudaGetSymbolAddress((void**)&p_xnei, g_xnei);
    cudaGetSymbolAddress((void**)&p_Bn, g_Bn);
    cudaGetSymbolAddress((void**)&p_Wd, g_Wd);
    cudaGetSymbolAddress((void**)&p_Wnc, g_Wnc);
    cudaGetSymbolAddress((void**)&p_Wqkv, g_Wqkv);
    cudaGetSymbolAddress((void**)&p_bqkv, g_bqkv);

    const int neigh_shmem = (64 * 129 * 2 + 128 + 128 + 256) * 4;            // ~68 KB
    const int au_shmem = (64 * 132 + 128 * 132 + 2048 + 64 * 16) * 4;        // 113664 B
    cudaFuncSetAttribute(neigh_kernel, cudaFuncAttributeMaxDynamicSharedMemorySize, neigh_shmem);
    cudaFuncSetAttribute(au_kernel, cudaFuncAttributeMaxDynamicSharedMemorySize, au_shmem);

    prep_kernel<<<192, 256>>>(au_w1, wq, wk, wv, bq, bk, bv, p_Wd, p_Wnc, p_Wqkv, p_bqkv);
    ln_kernel<<<ROWS, 128>>>(x, ln1_g, ln1_b, p_xn);
    {
        dim3 g(384 / TBN, ROWS / TBM);
        sgemm_tc<<<g, 256>>>(p_xn, p_Wqkv, p_bqkv, nullptr, p_qkv, ROWS, HH, 384, 0);
    }
    attn_kernel<<<BB * NHEADS * 8, 128>>>(p_qkv, mask, p_attn);
    {
        dim3 g(1, ROWS / TBM);
        sgemm_tc<<<g, 256>>>(p_attn, wo, bo, x, p_x1, ROWS, HH, HH, 0);
    }
    neigh_kernel<<<NN * BB, 256, neigh_shmem>>>(neighs, nmask, wq, bq, wk, bk, wv, bv,
                                                wo, bo, ln1_g, ln1_b, p_xnei);
    ln_kernel<<<ROWS, 128>>>(p_x1, ln2_g, ln2_b, p_h);
    {
        dim3 g(FFD / TBN, ROWS / TBM);
        sgemm_tc<<<g, 256>>>(p_h, ff_w1, ff_b1, nullptr, p_ffh, ROWS, HH, FFD, 1);
    }
    {
        dim3 g(1, ROWS / TBM);
        sgemm_tc<<<g, 256>>>(p_ffh, ff_w2, ff_b2, p_x1, p_x2, ROWS, FFD, HH, 0);
    }
    {
        dim3 g(1, ROWS / TBM);
        sgemm_tc<<<g, 256>>>(p_x2, p_Wd, au_b1, nullptr, p_A, ROWS, HH, HH, 0);
    }
    {
        dim3 g(1, (BB * NN) / TBM);
        sgemm_tc<<<g, 256>>>(p_xnei, p_Wnc, nullptr, nullptr, p_Bn, BB * NN, HH, HH, 0);
    }
    {
        dim3 g(SS / 64, BB);
        au_kernel<<<g, 256, au_shmem>>>(p_x2, p_A, p_Bn, p_xnei, au_w1, au_w2, au_b2, out);
    }
}

// round 5
// speedup vs baseline: 2.2626x; 1.0471x over previous
#include <cuda_runtime.h>
#include <cuda_bf16.h>
#include <math.h>

// Problem dims
#define BB 32
#define SS 512
#define HH 128
#define NHEADS 4
#define DD 32
#define FFD 512
#define NN 16
#define SNN 64
#define ROWS (BB*SS)          // 16384

// ---------------- static device scratch ----------------
__device__ float g_xn  [ROWS*HH];
__device__ float g_qkv [ROWS*384];
__device__ float g_attn[ROWS*HH];
__device__ float g_x1  [ROWS*HH];
__device__ float g_h   [ROWS*HH];
__device__ float g_ffh [ROWS*FFD];
__device__ float g_x2  [ROWS*HH];
__device__ float g_A   [ROWS*HH];
__device__ float g_xnei[BB*NN*HH];
__device__ float g_Bn  [BB*NN*HH];
__device__ float g_Wd  [HH*HH];
__device__ float g_Wnc [HH*HH];
__device__ float g_Wqkv[HH*384];
__device__ float g_bqkv[384];

// ---------------- tf32 / mma helpers --------------------------------------
__device__ __forceinline__ unsigned f2tf(float f) {
    unsigned r;
    asm("cvt.rna.tf32.f32 %0, %1;" : "=r"(r) : "f"(f));
    return r;
}
__device__ __forceinline__ float f2tf_f(float f) { return __uint_as_float(f2tf(f)); }

__device__ __forceinline__ void mma_tf32(float* c, const unsigned* a, const unsigned* b) {
    asm volatile(
        "mma.sync.aligned.m16n8k8.row.col.f32.tf32.tf32.f32 "
        "{%0,%1,%2,%3}, {%4,%5,%6,%7}, {%8,%9}, {%0,%1,%2,%3};"
        : "+f"(c[0]), "+f"(c[1]), "+f"(c[2]), "+f"(c[3])
        : "r"(a[0]), "r"(a[1]), "r"(a[2]), "r"(a[3]), "r"(b[0]), "r"(b[1]));
}

// ---------------- fast exp: FMA-pipe polynomial (no MUFU) ----------------
__device__ __forceinline__ float fast_exp(float x) {
    float z = x * 1.4426950408889634f;
    z = fminf(fmaxf(z, -126.0f), 126.0f);
    float t = z + 12582912.0f;
    int n = __float_as_int(t) - 0x4B400000;
    float f = z - (t - 12582912.0f);
    float p = 0.0013333558f;
    p = fmaf(p, f, 0.0096181291f);
    p = fmaf(p, f, 0.0555041087f);
    p = fmaf(p, f, 0.2402265070f);
    p = fmaf(p, f, 0.6931471806f);
    p = fmaf(p, f, 1.0f);
    return __int_as_float(__float_as_int(p) + (n << 23));
}

__device__ __forceinline__ float gelu_fast(float x) {
    float u = 0.7978845608028654f * (x + 0.044715f * x * x * x);
    float t = fast_exp(-2.0f * u);
    return __fdividef(x, 1.0f + t);
}

// ---------------- prep ------------------------------------------------------
__global__ void prep_kernel(const float* __restrict__ au_w1,
                            const float* __restrict__ wq, const float* __restrict__ wk,
                            const float* __restrict__ wv,
                            const float* __restrict__ bq, const float* __restrict__ bk,
                            const float* __restrict__ bv,
                            float* __restrict__ Wd, float* __restrict__ Wnc,
                            float* __restrict__ Wqkv, float* __restrict__ bqkv) {
    int idx = blockIdx.x * blockDim.x + threadIdx.x;
    if (idx < HH * HH) {
        int h = idx >> 7, j = idx & 127;
        float w1 = au_w1[h * HH + j];
        float w3 = au_w1[(256 + h) * HH + j];
        float w4 = au_w1[(384 + h) * HH + j];
        Wd[idx]  = w1 - w3;
        Wnc[idx] = w3 + w4;
    }
    if (idx < HH * 384) {
        int h = idx / 384, c = idx % 384;
        float v = (c < 128) ? wq[h * 128 + c]
                 : (c < 256) ? wk[h * 128 + (c - 128)]
                             : wv[h * 128 + (c - 256)];
        Wqkv[idx] = v;
    }
    if (idx < 384) {
        bqkv[idx] = (idx < 128) ? bq[idx] : (idx < 256) ? bk[idx - 128] : bv[idx - 256];
    }
}

// ---------------- layernorm ------------------------------------------------
__global__ void ln_kernel(const float* __restrict__ x, const float* __restrict__ g,
                          const float* __restrict__ b, float* __restrict__ y) {
    int row = blockIdx.x;
    int t = threadIdx.x;
    float v = x[(size_t)row * HH + t];
    float s = v, s2 = v * v;
    #pragma unroll
    for (int o = 16; o > 0; o >>= 1) {
        s  += __shfl_xor_sync(0xffffffffu, s, o);
        s2 += __shfl_xor_sync(0xffffffffu, s2, o);
    }
    __shared__ float ws[8];
    if ((t & 31) == 0) { ws[t >> 5] = s; ws[4 + (t >> 5)] = s2; }
    __syncthreads();
    s  = ws[0] + ws[1] + ws[2] + ws[3];
    s2 = ws[4] + ws[5] + ws[6] + ws[7];
    float mean = s * (1.0f / HH);
    float var = s2 * (1.0f / HH) - mean * mean;
    float rs = rsqrtf(var + 1e-6f);
    y[(size_t)row * HH + t] = (v - mean) * rs * g[t] + b[t];
}

// ---------------- TF32 tensor-core GEMM: 128x128 tile, 8 warps -------------
#define TBM 128
#define TBN 128
#define TBK 16
__global__ __launch_bounds__(256) void sgemm_tc(
    const float* __restrict__ A, const float* __restrict__ W,
    const float* __restrict__ bias, const float* __restrict__ res,
    float* __restrict__ C, int M, int K, int N, int act) {
    __shared__ float As[2][TBK][132];
    __shared__ float Ws[2][TBK][132];
    int bm = blockIdx.y * TBM, bn = blockIdx.x * TBN;
    int tid = threadIdx.x;
    int wid = tid >> 5, lane = tid & 31;
    int gid = lane >> 2, tig = lane & 3;
    int wm = (wid >> 2) * 64, wn = (wid & 3) * 32;
    int arow[2], ac4[2], wrow[2], wc4[2];
    #pragma unroll
    for (int l = 0; l < 2; l++) {
        int L = l * 256 + tid;
        arow[l] = L >> 2;  ac4[l] = L & 3;
        wrow[l] = L >> 5;  wc4[l] = L & 31;
    }
    float4 aL[2], wL[2];
    #pragma unroll
    for (int l = 0; l < 2; l++) {
        aL[l] = *(const float4*)&A[(size_t)(bm + arow[l]) * K + ac4[l] * 4];
        wL[l] = *(const float4*)&W[(size_t)wrow[l] * N + bn + wc4[l] * 4];
    }
    #pragma unroll
    for (int l = 0; l < 2; l++) {
        As[0][ac4[l] * 4 + 0][arow[l]] = f2tf_f(aL[l].x);
        As[0][ac4[l] * 4 + 1][arow[l]] = f2tf_f(aL[l].y);
        As[0][ac4[l] * 4 + 2][arow[l]] = f2tf_f(aL[l].z);
        As[0][ac4[l] * 4 + 3][arow[l]] = f2tf_f(aL[l].w);
        Ws[0][wrow[l]][wc4[l] * 4 + 0] = f2tf_f(wL[l].x);
        Ws[0][wrow[l]][wc4[l] * 4 + 1] = f2tf_f(wL[l].y);
        Ws[0][wrow[l]][wc4[l] * 4 + 2] = f2tf_f(wL[l].z);
        Ws[0][wrow[l]][wc4[l] * 4 + 3] = f2tf_f(wL[l].w);
    }
    __syncthreads();
    float c[4][4][4] = {};
    int nk = K / TBK;
    for (int kt = 0; kt < nk; kt++) {
        int cur = kt & 1;
        if (kt + 1 < nk) {
            int k0 = (kt + 1) * TBK;
            #pragma unroll
            for (int l = 0; l < 2; l++) {
                aL[l] = *(const float4*)&A[(size_t)(bm + arow[l]) * K + k0 + ac4[l] * 4];
                wL[l] = *(const float4*)&W[(size_t)(k0 + wrow[l]) * N + bn + wc4[l] * 4];
            }
        }
        #pragma unroll
        for (int ks = 0; ks < 2; ks++) {
            int k0 = ks * 8;
            unsigned a[4][4], b[4][2];
            #pragma unroll
            for (int mt = 0; mt < 4; mt++) {
                a[mt][0] = __float_as_uint(As[cur][k0 + tig    ][wm + mt * 16 + gid]);
                a[mt][1] = __float_as_uint(As[cur][k0 + tig    ][wm + mt * 16 + gid + 8]);
                a[mt][2] = __float_as_uint(As[cur][k0 + tig + 4][wm + mt * 16 + gid]);
                a[mt][3] = __float_as_uint(As[cur][k0 + tig + 4][wm + mt * 16 + gid + 8]);
            }
            #pragma unroll
            for (int nt = 0; nt < 4; nt++) {
                b[nt][0] = __float_as_uint(Ws[cur][k0 + tig    ][wn + nt * 8 + gid]);
                b[nt][1] = __float_as_uint(Ws[cur][k0 + tig + 4][wn + nt * 8 + gid]);
            }
            #pragma unroll
            for (int mt = 0; mt < 4; mt++)
                #pragma unroll
                for (int nt = 0; nt < 4; nt++)
                    mma_tf32(c[mt][nt], a[mt], b[nt]);
        }
        if (kt + 1 < nk) {
            int nxt = cur ^ 1;
            #pragma unroll
            for (int l = 0; l < 2; l++) {
                As[nxt][ac4[l] * 4 + 0][arow[l]] = f2tf_f(aL[l].x);
                As[nxt][ac4[l] * 4 + 1][arow[l]] = f2tf_f(aL[l].y);
                As[nxt][ac4[l] * 4 + 2][arow[l]] = f2tf_f(aL[l].z);
                As[nxt][ac4[l] * 4 + 3][arow[l]] = f2tf_f(aL[l].w);
                Ws[nxt][wrow[l]][wc4[l] * 4 + 0] = f2tf_f(wL[l].x);
                Ws[nxt][wrow[l]][wc4[l] * 4 + 1] = f2tf_f(wL[l].y);
                Ws[nxt][wrow[l]][wc4[l] * 4 + 2] = f2tf_f(wL[l].z);
                Ws[nxt][wrow[l]][wc4[l] * 4 + 3] = f2tf_f(wL[l].w);
            }
        }
        __syncthreads();
    }
    // epilogue
    #pragma unroll
    for (int mt = 0; mt < 4; mt++) {
        #pragma unroll
        for (int nt = 0; nt < 4; nt++) {
            int col = bn + wn + nt * 8 + tig * 2;
            float b0 = bias ? bias[col] : 0.0f;
            float b1 = bias ? bias[col + 1] : 0.0f;
            #pragma unroll
            for (int hh = 0; hh < 2; hh++) {
                int row = bm + wm + mt * 16 + gid + hh * 8;
                float v0 = c[mt][nt][hh * 2 + 0] + b0;
                float v1 = c[mt][nt][hh * 2 + 1] + b1;
                if (act == 1) { v0 = gelu_fast(v0); v1 = gelu_fast(v1); }
                if (res) {
                    const float2 rv = *(const float2*)&res[(size_t)row * N + col];
                    v0 += rv.x; v1 += rv.y;
                }
                float2 ov; ov.x = v0; ov.y = v1;
                *(float2*)&C[(size_t)row * N + col] = ov;
            }
        }
    }
}

// ---------------- flash attention with tf32 mma, shuffle P-relayout --------
// block = (b, h, q-tile 64); 128 threads (4 warps), warp w owns q rows w*16..+15
__global__ __launch_bounds__(128) void attn_kernel(const float* __restrict__ qkv,
                                                   const int* __restrict__ mask,
                                                   float* __restrict__ o) {
    __shared__ float Qs[64][36];
    __shared__ float Ks[64][36];
    __shared__ float Vs[64][36];
    int blk = blockIdx.x;
    int qt = blk & 7, h = (blk >> 3) & 3, b = blk >> 5;
    int q0 = qt * 64;
    int tid = threadIdx.x;
    int w = tid >> 5, lane = tid & 31;
    int gid = lane >> 2, tig = lane & 3;
    const float* qbase = qkv + (size_t)(b * SS + q0) * 384 + h * 32;
    const float scale = 0.17677669529663687f;
    #pragma unroll
    for (int k = 0; k < 4; k++) {
        int idx = tid + k * 128;
        int r = idx >> 3, c4 = idx & 7;
        float4 v = *(const float4*)&qbase[(size_t)r * 384 + c4 * 4];
        Qs[r][c4 * 4 + 0] = f2tf_f(v.x * scale);
        Qs[r][c4 * 4 + 1] = f2tf_f(v.y * scale);
        Qs[r][c4 * 4 + 2] = f2tf_f(v.z * scale);
        Qs[r][c4 * 4 + 3] = f2tf_f(v.w * scale);
    }
    float o_acc[4][4] = {};
    float m0 = -1e30f, l0 = 0.0f, m1 = -1e30f, l1 = 0.0f;
    const int* mbase = mask + (size_t)b * SS * SS + (size_t)q0 * SS;
    const float* kbase = qkv + (size_t)b * SS * 384 + 128 + h * 32;
    const float* vbase = qkv + (size_t)b * SS * 384 + 256 + h * 32;
    int src0 = (lane & ~3) + (tig >> 1);
    int src2 = src0 + 2;
    bool oddc = (tig & 1) != 0;
    for (int kt = 0; kt < 8; kt++) {
        int c0k = kt * 64;
        __syncthreads();
        #pragma unroll
        for (int k = 0; k < 4; k++) {
            int idx = tid + k * 128;
            int r = idx >> 3, c4 = idx & 7;
            float4 kv4 = *(const float4*)&kbase[(size_t)(c0k + r) * 384 + c4 * 4];
            float4 vv4 = *(const float4*)&vbase[(size_t)(c0k + r) * 384 + c4 * 4];
            Ks[r][c4 * 4 + 0] = f2tf_f(kv4.x);
            Ks[r][c4 * 4 + 1] = f2tf_f(kv4.y);
            Ks[r][c4 * 4 + 2] = f2tf_f(kv4.z);
            Ks[r][c4 * 4 + 3] = f2tf_f(kv4.w);
            Vs[r][c4 * 4 + 0] = f2tf_f(vv4.x);
            Vs[r][c4 * 4 + 1] = f2tf_f(vv4.y);
            Vs[r][c4 * 4 + 2] = f2tf_f(vv4.z);
            Vs[r][c4 * 4 + 3] = f2tf_f(vv4.w);
        }
        __syncthreads();
        // S = Q @ K^T : per-warp 16x64
        float cs[8][4] = {};
        #pragma unroll
        for (int ks = 0; ks < 4; ks++) {
            int k0 = ks * 8;
            unsigned a[4];
            a[0] = __float_as_uint(Qs[w * 16 + gid    ][k0 + tig]);
            a[1] = __float_as_uint(Qs[w * 16 + gid + 8][k0 + tig]);
            a[2] = __float_as_uint(Qs[w * 16 + gid    ][k0 + tig + 4]);
            a[3] = __float_as_uint(Qs[w * 16 + gid + 8][k0 + tig + 4]);
            #pragma unroll
            for (int nt = 0; nt < 8; nt++) {
                unsigned bb[2];
                bb[0] = __float_as_uint(Ks[nt * 8 + gid][k0 + tig]);
                bb[1] = __float_as_uint(Ks[nt * 8 + gid][k0 + tig + 4]);
                mma_tf32(cs[nt], a, bb);
            }
        }
        // mask (int2) + online softmax (rows r0 = w*16+gid, r1 = +8)
        const int2* mr0 = (const int2*)(mbase + (size_t)(w * 16 + gid) * SS + c0k);
        const int2* mr1 = (const int2*)(mbase + (size_t)(w * 16 + gid + 8) * SS + c0k);
        float sv0[16], sv1[16];
        #pragma unroll
        for (int nt = 0; nt < 8; nt++) {
            int2 m0v = mr0[nt * 4 + tig];
            int2 m1v = mr1[nt * 4 + tig];
            float s;
            s = cs[nt][0]; if (m0v.x == 0) s = -1e9f; sv0[nt * 2 + 0] = s;
            s = cs[nt][1]; if (m0v.y == 0) s = -1e9f; sv0[nt * 2 + 1] = s;
            s = cs[nt][2]; if (m1v.x == 0) s = -1e9f; sv1[nt * 2 + 0] = s;
            s = cs[nt][3]; if (m1v.y == 0) s = -1e9f; sv1[nt * 2 + 1] = s;
        }
        float t0 = sv0[0], t1 = sv1[0];
        #pragma unroll
        for (int i = 1; i < 16; i++) { t0 = fmaxf(t0, sv0[i]); t1 = fmaxf(t1, sv1[i]); }
        t0 = fmaxf(t0, __shfl_xor_sync(0xffffffffu, t0, 1));
        t0 = fmaxf(t0, __shfl_xor_sync(0xffffffffu, t0, 2));
        t1 = fmaxf(t1, __shfl_xor_sync(0xffffffffu, t1, 1));
        t1 = fmaxf(t1, __shfl_xor_sync(0xffffffffu, t1, 2));
        float mn0 = fmaxf(m0, t0), mn1 = fmaxf(m1, t1);
        float corr0 = fast_exp(m0 - mn0), corr1 = fast_exp(m1 - mn1);
        float ps0 = 0.0f, ps1 = 0.0f;
        #pragma unroll
        for (int i = 0; i < 16; i++) {
            float p0 = fast_exp(sv0[i] - mn0);
            float p1 = fast_exp(sv1[i] - mn1);
            sv0[i] = p0; sv1[i] = p1;
            ps0 += p0; ps1 += p1;
        }
        ps0 += __shfl_xor_sync(0xffffffffu, ps0, 1);
        ps0 += __shfl_xor_sync(0xffffffffu, ps0, 2);
        ps1 += __shfl_xor_sync(0xffffffffu, ps1, 1);
        ps1 += __shfl_xor_sync(0xffffffffu, ps1, 2);
        l0 = l0 * corr0 + ps0; m0 = mn0;
        l1 = l1 * corr1 + ps1; m1 = mn1;
        #pragma unroll
        for (int nt = 0; nt < 4; nt++) {
            o_acc[nt][0] *= corr0; o_acc[nt][1] *= corr0;
            o_acc[nt][2] *= corr1; o_acc[nt][3] *= corr1;
        }
        // O += P @ V : P fragments via intra-quad shuffles (no smem round-trip)
        #pragma unroll
        for (int ks = 0; ks < 8; ks++) {
            float lo0 = __shfl_sync(0xffffffffu, sv0[ks * 2    ], src0);
            float hi0 = __shfl_sync(0xffffffffu, sv0[ks * 2 + 1], src0);
            float lo1 = __shfl_sync(0xffffffffu, sv1[ks * 2    ], src0);
            float hi1 = __shfl_sync(0xffffffffu, sv1[ks * 2 + 1], src0);
            float lo2 = __shfl_sync(0xffffffffu, sv0[ks * 2    ], src2);
            float hi2 = __shfl_sync(0xffffffffu, sv0[ks * 2 + 1], src2);
            float lo3 = __shfl_sync(0xffffffffu, sv1[ks * 2    ], src2);
            float hi3 = __shfl_sync(0xffffffffu, sv1[ks * 2 + 1], src2);
            unsigned a[4];
            a[0] = f2tf(oddc ? hi0 : lo0);
            a[1] = f2tf(oddc ? hi1 : lo1);
            a[2] = f2tf(oddc ? hi2 : lo2);
            a[3] = f2tf(oddc ? hi3 : lo3);
            int k0 = ks * 8;
            #pragma unroll
            for (int nt = 0; nt < 4; nt++) {
                unsigned bb[2];
                bb[0] = __float_as_uint(Vs[k0 + tig    ][nt * 8 + gid]);
                bb[1] = __float_as_uint(Vs[k0 + tig + 4][nt * 8 + gid]);
                mma_tf32(o_acc[nt], a, bb);
            }
        }
    }
    // epilogue
    float inv0 = __fdividef(1.0f, l0);
    float inv1 = __fdividef(1.0f, l1);
    #pragma unroll
    for (int nt = 0; nt < 4; nt++) {
        int col = h * 32 + nt * 8 + tig * 2;
        size_t row0 = (size_t)(b * SS + q0 + w * 16 + gid);
        float2 v0; v0.x = o_acc[nt][0] * inv0; v0.y = o_acc[nt][1] * inv0;
        *(float2*)&o[row0 * HH + col] = v0;
        float2 v1; v1.x = o_acc[nt][2] * inv1; v1.y = o_acc[nt][3] * inv1;
        *(float2*)&o[(row0 + 8) * HH + col] = v1;
    }
}

// ---------------- neighbor proj helper -------------------------------------
__device__ __forceinline__ void proj64(const float* ln, const float* __restrict__ W,
                                       const float* __restrict__ bias, float* out, int tid) {
    int c2 = (tid & 63) * 2;
    int q4 = tid >> 6;
    int r0 = q4 * 16;
    float acc0[16], acc1[16];
    float bv0 = bias[c2], bv1 = bias[c2 + 1];
    #pragma unroll
    for (int i = 0; i < 16; i++) { acc0[i] = bv0; acc1[i] = bv1; }
    #pragma unroll 4
    for (int hh = 0; hh < HH; hh++) {
        float2 w = *(const float2*)&W[hh * HH + c2];
        #pragma unroll
        for (int i = 0; i < 16; i++) {
            float a = ln[(r0 + i) * 129 + hh];
            acc0[i] += a * w.x;
            acc1[i] += a * w.y;
        }
    }
    #pragma unroll
    for (int i = 0; i < 16; i++) {
        out[(r0 + i) * 129 + c2] = acc0[i];
        out[(r0 + i) * 129 + c2 + 1] = acc1[i];
    }
}

// ---------------- neighbor attention (last-token only) ---------------------
__global__ void neigh_kernel(const float* __restrict__ neighs, const int* __restrict__ nmask,
                             const float* __restrict__ wq, const float* __restrict__ bq,
                             const float* __restrict__ wk, const float* __restrict__ bk,
                             const float* __restrict__ wv, const float* __restrict__ bv,
                             const float* __restrict__ wo, const float* __restrict__ bo,
                             const float* __restrict__ g1, const float* __restrict__ b1,
                             float* __restrict__ xnei) {
    extern __shared__ float sh[];
    float* ln  = sh;
    float* kv  = ln + 64 * 129;
    float* qv  = kv + 64 * 129;
    float* osh = qv + 128;
    float* sc  = osh + 128;
    int tid = threadIdx.x;
    int nb = blockIdx.x;
    int n = nb / BB, b = nb % BB;
    const float* base = neighs + (size_t)nb * SNN * HH;
    for (int idx = tid; idx < SNN * HH; idx += 256) {
        int r = idx >> 7, c = idx & 127;
        ln[r * 129 + c] = base[idx];
    }
    __syncthreads();
    {
        int warp = tid >> 5, lane = tid & 31;
        for (int r = warp; r < SNN; r += 8) {
            float s = 0.0f, s2 = 0.0f;
            #pragma unroll
            for (int c = lane; c < HH; c += 32) {
                float v = ln[r * 129 + c];
                s += v; s2 += v * v;
            }
            #pragma unroll
            for (int o = 16; o > 0; o >>= 1) {
                s  += __shfl_xor_sync(0xffffffffu, s, o);
                s2 += __shfl_xor_sync(0xffffffffu, s2, o);
            }
            float mean = s * (1.0f / HH);
            float var = s2 * (1.0f / HH) - mean * mean;
            float rs = rsqrtf(var + 1e-6f);
            #pragma unroll
            for (int c = lane; c < HH; c += 32) {
                float v = ln[r * 129 + c];
                ln[r * 129 + c] = (v - mean) * rs * g1[c] + b1[c];
            }
        }
    }
    __syncthreads();
    proj64(ln, wk, bk, kv, tid);
    if (tid < HH) {
        float a = bq[tid];
        #pragma unroll 4
        for (int hh = 0; hh < HH; hh++) a += ln[63 * 129 + hh] * wq[hh * HH + tid];
        qv[tid] = a;
    }
    __syncthreads();
    {
        int head = tid >> 6, j = tid & 63;
        float s = 0.0f;
        #pragma unroll
        for (int d = 0; d < DD; d++) s += qv[head * DD + d] * kv[j * 129 + head * DD + d];
        s *= 0.17677669529663687f;
        int mval = nmask[((size_t)nb * SNN + (SNN - 1)) * SNN + j];
        if (mval == 0) s = -1e9f;
        sc[head * 64 + j] = s;
    }
    __syncthreads();
    if (tid < 4) {
        float m = -1e30f;
        for (int j = 0; j < 64; j++) m = fmaxf(m, sc[tid * 64 + j]);
        float l = 0.0f;
        for (int j = 0; j < 64; j++) {
            float p = fast_exp(sc[tid * 64 + j] - m);
            sc[tid * 64 + j] = p; l += p;
        }
        float inv = 1.0f / l;
        for (int j = 0; j < 64; j++) sc[tid * 64 + j] *= inv;
    }
    __syncthreads();
    proj64(ln, wv, bv, kv, tid);
    __syncthreads();
    if (tid < HH) {
        int head = tid >> 5;
        float o = 0.0f;
        #pragma unroll 4
        for (int j = 0; j < 64; j++) o += sc[head * 64 + j] * kv[j * 129 + tid];
        osh[tid] = o;
    }
    __syncthreads();
    if (tid < HH) {
        float r = bo[tid] + base[(SNN - 1) * HH + tid];
        #pragma unroll 4
        for (int hh = 0; hh < HH; hh++) r += osh[hh] * wo[hh * HH + tid];
        xnei[((size_t)b * NN + n) * HH + tid] = r;
    }
}

// ---------------- attention-pooling kernel (tf32 mma, B-scaled) ------------
// block = (b, 64 s-rows), 256 threads (8 warps). warp w owns W2-cols w*16..+15.
// (x∘ne)@W2 == x @ (diag(ne)@W2): scale the 4 B-fragments by ne instead of the
// 16 A-fragments. x2s pre-converted to tf32 so A fragments are plain LDS.
__global__ __launch_bounds__(256) void au_kernel(
        const float* __restrict__ x2, const float* __restrict__ Ag,
        const float* __restrict__ Bng, const float* __restrict__ xnei,
        const float* __restrict__ au_w1, const float* __restrict__ au_w2,
        const float* __restrict__ au_b2, float* __restrict__ out) {
    extern __shared__ float sh[];
    float* x2s    = sh;                  // 64*132 tf32
    float* W2s    = x2s + 64 * 132;      // 128*132 tf32
    float* xns    = W2s + 128 * 132;     // 16*128 fp32
    float* logits = xns + 2048;          // 64*16
    int tid = threadIdx.x;
    int b = blockIdx.y;
    int s0 = blockIdx.x * 64;
    int w = tid >> 5, lane = tid & 31;
    int gid = lane >> 2, tig = lane & 3;
    int wn = w * 16;
    for (int idx = tid; idx < HH * HH; idx += 256) {
        int k = idx >> 7, nn = idx & 127;
        W2s[k * 132 + nn] = f2tf_f(au_w1[HH * HH + idx]);
    }
    for (int idx = tid; idx < 64 * HH; idx += 256) {
        int r = idx >> 7, cc = idx & 127;
        x2s[r * 132 + cc] = f2tf_f(x2[((size_t)b * SS + s0 + r) * HH + cc]);
    }
    for (int idx = tid; idx < NN * HH; idx += 256) xns[idx] = xnei[(size_t)b * NN * HH + idx];
    for (int idx = tid; idx < 64 * 16; idx += 256) logits[idx] = 0.0f;
    // per-thread fixed columns
    int colv[4];
    float w2r[4];
    #pragma unroll
    for (int q = 0; q < 4; q++) {
        colv[q] = wn + (q >> 1) * 8 + tig * 2 + (q & 1);
        w2r[q] = au_w2[colv[q]];
    }
    float Areg[8][4];
    #pragma unroll
    for (int mt = 0; mt < 4; mt++)
        #pragma unroll
        for (int hh = 0; hh < 2; hh++) {
            int r = mt * 16 + gid + hh * 8;
            #pragma unroll
            for (int q = 0; q < 4; q++)
                Areg[mt * 2 + hh][q] = Ag[((size_t)b * SS + s0 + r) * HH + colv[q]];
        }
    __syncthreads();
    for (int n = 0; n < NN; n++) {
        const float* xnp = xns + n * 128;
        float c[4][2][4] = {};
        #pragma unroll
        for (int ks = 0; ks < 16; ks++) {
            int k0 = ks * 8;
            float xn0 = xnp[k0 + tig];
            float xn4 = xnp[k0 + tig + 4];
            unsigned bfr[2][2];
            #pragma unroll
            for (int nt = 0; nt < 2; nt++) {
                bfr[nt][0] = f2tf(W2s[(k0 + tig) * 132 + wn + nt * 8 + gid] * xn0);
                bfr[nt][1] = f2tf(W2s[(k0 + tig + 4) * 132 + wn + nt * 8 + gid] * xn4);
            }
            #pragma unroll
            for (int mt = 0; mt < 4; mt++) {
                unsigned a[4];
                a[0] = __float_as_uint(x2s[(mt * 16 + gid) * 132 + k0 + tig]);
                a[1] = __float_as_uint(x2s[(mt * 16 + gid + 8) * 132 + k0 + tig]);
                a[2] = __float_as_uint(x2s[(mt * 16 + gid) * 132 + k0 + tig + 4]);
                a[3] = __float_as_uint(x2s[(mt * 16 + gid + 8) * 132 + k0 + tig + 4]);
                mma_tf32(c[mt][0], a, bfr[0]);
                mma_tf32(c[mt][1], a, bfr[1]);
            }
        }
        float BnR[4];
        #pragma unroll
        for (int q = 0; q < 4; q++)
            BnR[q] = Bng[((size_t)b * NN + n) * HH + colv[q]];
        #pragma unroll
        for (int mt = 0; mt < 4; mt++) {
            float part0 = 0.0f, part1 = 0.0f;
            #pragma unroll
            for (int nt = 0; nt < 2; nt++)
                #pragma unroll
                for (int cc = 0; cc < 2; cc++) {
                    int q = nt * 2 + cc;
                    float v0 = c[mt][nt][cc]     + Areg[mt * 2][q]     + BnR[q];
                    float v1 = c[mt][nt][2 + cc] + Areg[mt * 2 + 1][q] + BnR[q];
                    part0 += fmaxf(v0, 0.0f) * w2r[q];
                    part1 += fmaxf(v1, 0.0f) * w2r[q];
                }
            part0 += __shfl_xor_sync(0xffffffffu, part0, 1);
            part0 += __shfl_xor_sync(0xffffffffu, part0, 2);
            part1 += __shfl_xor_sync(0xffffffffu, part1, 1);
            part1 += __shfl_xor_sync(0xffffffffu, part1, 2);
            if (tig == 0) {
                atomicAdd(&logits[(mt * 16 + gid) * 16 + n], part0);
                atomicAdd(&logits[(mt * 16 + gid + 8) * 16 + n], part1);
            }
        }
    }
    __syncthreads();
    if (tid < 64) {
        float m = -1e30f;
        #pragma unroll
        for (int n = 0; n < NN; n++) m = fmaxf(m, logits[tid * 16 + n]);
        float l = 0.0f;
        #pragma unroll
        for (int n = 0; n < NN; n++) {
            float p = fast_exp(logits[tid * 16 + n] - m);
            logits[tid * 16 + n] = p; l += p;
        }
        float inv = __fdividef(1.0f, l);
        #pragma unroll
        for (int n = 0; n < NN; n++) logits[tid * 16 + n] *= inv;
    }
    __syncthreads();
    for (int idx = tid; idx < 64 * HH; idx += 256) {
        int r = idx >> 7, cc = idx & 127;
        float o = x2[((size_t)b * SS + s0 + r) * HH + cc];
        #pragma unroll
        for (int n = 0; n < NN; n++) o += logits[r * 16 + n] * xns[n * HH + cc];
        out[((size_t)b * SS + s0 + r) * HH + cc] = o;
    }
}

// ---------------- launch ----------------
extern "C" void kernel_launch(void* const* d_in, const int* in_sizes, int n_in,
                              void* d_out, int out_size) {
    const float* x      = (const float*)d_in[0];
    const int*   mask   = (const int*)  d_in[1];
    const float* neighs = (const float*)d_in[2];
    const int*   nmask  = (const int*)  d_in[3];
    const float* wq = (const float*)d_in[4];  const float* bq = (const float*)d_in[5];
    const float* wk = (const float*)d_in[6];  const float* bk = (const float*)d_in[7];
    const float* wv = (const float*)d_in[8];  const float* bv = (const float*)d_in[9];
    const float* wo = (const float*)d_in[10]; const float* bo = (const float*)d_in[11];
    const float* ln1_g = (const float*)d_in[12]; const float* ln1_b = (const float*)d_in[13];
    const float* ln2_g = (const float*)d_in[14]; const float* ln2_b = (const float*)d_in[15];
    const float* ff_w1 = (const float*)d_in[16]; const float* ff_b1 = (const float*)d_in[17];
    const float* ff_w2 = (const float*)d_in[18]; const float* ff_b2 = (const float*)d_in[19];
    const float* au_w1 = (const float*)d_in[20]; const float* au_b1 = (const float*)d_in[21];
    const float* au_w2 = (const float*)d_in[22]; const float* au_b2 = (const float*)d_in[23];
    float* out = (float*)d_out;

    float *p_xn, *p_qkv, *p_attn, *p_x1, *p_h, *p_ffh, *p_x2, *p_A,
          *p_xnei, *p_Bn, *p_Wd, *p_Wnc, *p_Wqkv, *p_bqkv;
    cudaGetSymbolAddress((void**)&p_xn, g_xn);
    cudaGetSymbolAddress((void**)&p_qkv, g_qkv);
    cudaGetSymbolAddress((void**)&p_attn, g_attn);
    cudaGetSymbolAddress((void**)&p_x1, g_x1);
    cudaGetSymbolAddress((void**)&p_h, g_h);
    cudaGetSymbolAddress((void**)&p_ffh, g_ffh);
    cudaGetSymbolAddress((void**)&p_x2, g_x2);
    cudaGetSymbolAddress((void**)&p_A, g_A);
    cudaGetSymbolAddress((void**)&p_xnei, g_xnei);
    cudaGetSymbolAddress((void**)&p_Bn, g_Bn);
    cudaGetSymbolAddress((void**)&p_Wd, g_Wd);
    cudaGetSymbolAddress((void**)&p_Wnc, g_Wnc);
    cudaGetSymbolAddress((void**)&p_Wqkv, g_Wqkv);
    cudaGetSymbolAddress((void**)&p_bqkv, g_bqkv);

    const int neigh_shmem = (64 * 129 * 2 + 128 + 128 + 256) * 4;            // ~68 KB
    const int au_shmem = (64 * 132 + 128 * 132 + 2048 + 64 * 16) * 4;        // 113664 B
    cudaFuncSetAttribute(neigh_kernel, cudaFuncAttributeMaxDynamicSharedMemorySize, neigh_shmem);
    cudaFuncSetAttribute(au_kernel, cudaFuncAttributeMaxDynamicSharedMemorySize, au_shmem);

    prep_kernel<<<192, 256>>>(au_w1, wq, wk, wv, bq, bk, bv, p_Wd, p_Wnc, p_Wqkv, p_bqkv);
    ln_kernel<<<ROWS, 128>>>(x, ln1_g, ln1_b, p_xn);
    {
        dim3 g(384 / TBN, ROWS / TBM);
        sgemm_tc<<<g, 256>>>(p_xn, p_Wqkv, p_bqkv, nullptr, p_qkv, ROWS, HH, 384, 0);
    }
    attn_kernel<<<BB * NHEADS * 8, 128>>>(p_qkv, mask, p_attn);
    {
        dim3 g(1, ROWS / TBM);
        sgemm_tc<<<g, 256>>>(p_attn, wo, bo, x, p_x1, ROWS, HH, HH, 0);
    }
    neigh_kernel<<<NN * BB, 256, neigh_shmem>>>(neighs, nmask, wq, bq, wk, bk, wv, bv,
                                                wo, bo, ln1_g, ln1_b, p_xnei);
    ln_kernel<<<ROWS, 128>>>(p_x1, ln2_g, ln2_b, p_h);
    {
        dim3 g(FFD / TBN, ROWS / TBM);
        sgemm_tc<<<g, 256>>>(p_h, ff_w1, ff_b1, nullptr, p_ffh, ROWS, HH, FFD, 1);
    }
    {
        dim3 g(1, ROWS / TBM);
        sgemm_tc<<<g, 256>>>(p_ffh, ff_w2, ff_b2, p_x1, p_x2, ROWS, FFD, HH, 0);
    }
    {
        dim3 g(1, ROWS / TBM);
        sgemm_tc<<<g, 256>>>(p_x2, p_Wd, au_b1, nullptr, p_A, ROWS, HH, HH, 0);
    }
    {
        dim3 g(1, (BB * NN) / TBM);
        sgemm_tc<<<g, 256>>>(p_xnei, p_Wnc, nullptr, nullptr, p_Bn, BB * NN, HH, HH, 0);
    }
    {
        dim3 g(SS / 64, BB);
        au_kernel<<<g, 256, au_shmem>>>(p_x2, p_A, p_Bn, p_xnei, au_w1, au_w2, au_b2, out);
    }
}